// round 2
// baseline (speedup 1.0000x reference)
#include <cuda_runtime.h>
#include <math.h>

typedef unsigned long long ull;

// Problem dims
#define NB 4096
#define TT 128
#define KV 64
#define EE 35
#define LL 200
#define GE3 105
#define LE 235

#define NTH 800   // 100 jt-groups x 8 bt
#define BBLK 32
#define NCTA (NB / BBLK)   // 128

#define KP_H 100   // k-pairs for K=200 matrices
#define KP_X 18    // k-pairs for K=35 padded to 36

// Output layout: concat(pred[B,T,K], mu[B,L], logvar[B,L], predY[B,1])
#define PRED_OFF ((size_t)0)
#define MU_OFF   ((size_t)NB * TT * KV)
#define LV_OFF   (MU_OFF + (size_t)NB * LL)
#define PY_OFF   (LV_OFF + (size_t)NB * LL)

// Packed weight buffers: [warpj(25)][gate(3)][jj(2)][kp(KP)][jt4(4)][w0,w0,w1,w1]
__device__ float g_wih0[25 * 3 * 2 * KP_X * 16];   //  43200 floats
__device__ float g_whh0[25 * 3 * 2 * KP_H * 16];   // 240000
__device__ float g_wih1[25 * 3 * 2 * KP_H * 16];
__device__ float g_whh1[25 * 3 * 2 * KP_H * 16];

// SMEM arena (floats)
#define OFF_EMB 0        // 2240
#define OFF_H1  2240     // 6400
#define OFF_H2  8640     // 6400
#define OFF_XE  15040    // 1152 (36 rows x 32, row 35 = zero pad)
#define OFF_ZS  16192    // 6400
#define OFF_MU  22592    // 6400
#define OFF_GZ  28992    // 3360
#define OFF_G1  32352    // 3360
#define OFF_HD  35712    // 1120
#define SMEM_FLOATS 36832

__device__ __forceinline__ float sigm(float v) { return 1.0f / (1.0f + expf(-v)); }

__device__ __forceinline__ ull ffma2(ull a, ull b, ull c) {
    ull d;
    asm("fma.rn.f32x2 %0, %1, %2, %3;" : "=l"(d) : "l"(a), "l"(b), "l"(c));
    return d;
}
__device__ __forceinline__ ull pack2(float f) {
    unsigned u = __float_as_uint(f);
    return ((ull)u << 32) | u;
}
__device__ __forceinline__ float lo2(ull v) { return __uint_as_float((unsigned)v); }
__device__ __forceinline__ float hi2(ull v) { return __uint_as_float((unsigned)(v >> 32)); }

// ---- prep: permute+duplicate weights so one warp LDG.128 = 1 wavefront ----
__global__ void pack_weights(const float* __restrict__ src, int which, int K, int KP) {
    float* dst = (which == 0) ? g_wih0 : (which == 1) ? g_whh0
               : (which == 2) ? g_wih1 : g_whh1;
    int idx = blockIdx.x * blockDim.x + threadIdx.x;   // one float4 group each
    int total = 25 * 3 * 2 * KP * 4;
    if (idx >= total) return;
    int jt4 = idx & 3;
    int r = idx >> 2;
    int kp = r % KP; r /= KP;
    int jj = r & 1;  r >>= 1;
    int gate = r % 3; r /= 3;
    int warpj = r;
    int j   = (warpj * 4 + jt4) * 2 + jj;
    int row = gate * LL + j;
    int k0 = kp * 2, k1 = k0 + 1;
    float w0 = (k0 < K) ? src[row * K + k0] : 0.0f;
    float w1 = (k1 < K) ? src[row * K + k1] : 0.0f;
    ((float4*)dst)[idx] = make_float4(w0, w0, w1, w1);
}

// One GEMM fragment: acc over K into (ar, az, a3) for this thread's 2 j x 2 b-pairs.
// acts: SMEM [k][32] rows; wpack: packed weight buffer; KP: k-pairs.
__device__ __forceinline__ void gemm_part(const float* __restrict__ acts,
                                          const float* __restrict__ wpack, int KP,
                                          ull (&ar)[2][2], ull (&az)[2][2], ull (&a3)[2][2],
                                          int warpj, int jt4, int b0)
{
    const ulonglong2* wp = (const ulonglong2*)wpack;
    // base index (in ulonglong2 units of 16B): (((warpj*3+g)*2+jj)*KP + kp)*4 + jt4
    int base = warpj * 6 * KP * 4 + jt4;
    #pragma unroll 2
    for (int kp = 0; kp < KP; kp++) {
        ulonglong2 a0 = *(const ulonglong2*)(acts + (2 * kp) * 32 + b0);
        ulonglong2 a1 = *(const ulonglong2*)(acts + (2 * kp + 1) * 32 + b0);
        #pragma unroll
        for (int jj = 0; jj < 2; jj++) {
            ulonglong2 wr = wp[base + (0 + jj) * KP * 4 + kp * 4];
            ulonglong2 wz = wp[base + (2 + jj) * KP * 4 + kp * 4];
            ulonglong2 wn = wp[base + (4 + jj) * KP * 4 + kp * 4];
            ar[jj][0] = ffma2(wr.x, a0.x, ar[jj][0]);
            ar[jj][1] = ffma2(wr.x, a0.y, ar[jj][1]);
            ar[jj][0] = ffma2(wr.y, a1.x, ar[jj][0]);
            ar[jj][1] = ffma2(wr.y, a1.y, ar[jj][1]);
            az[jj][0] = ffma2(wz.x, a0.x, az[jj][0]);
            az[jj][1] = ffma2(wz.x, a0.y, az[jj][1]);
            az[jj][0] = ffma2(wz.y, a1.x, az[jj][0]);
            az[jj][1] = ffma2(wz.y, a1.y, az[jj][1]);
            a3[jj][0] = ffma2(wn.x, a0.x, a3[jj][0]);
            a3[jj][1] = ffma2(wn.x, a0.y, a3[jj][1]);
            a3[jj][0] = ffma2(wn.y, a1.x, a3[jj][0]);
            a3[jj][1] = ffma2(wn.y, a1.y, a3[jj][1]);
        }
    }
}

extern "C" __global__ void __launch_bounds__(NTH, 1)
vae_all(const int* __restrict__ x, const float* __restrict__ emb,
        const float* __restrict__ eb_ih0, const float* __restrict__ eb_hh0,
        const float* __restrict__ eb_ih1, const float* __restrict__ eb_hh1,
        const float* __restrict__ dW_ih0, const float* __restrict__ db_ih0,
        const float* __restrict__ db_hh0,
        const float* __restrict__ dW_ih1, const float* __restrict__ db_ih1,
        const float* __restrict__ db_hh1,
        const float* __restrict__ fc11_w, const float* __restrict__ fc11_b,
        const float* __restrict__ fc12_w, const float* __restrict__ fc12_b,
        const float* __restrict__ p1_w,  const float* __restrict__ p1_b,
        const float* __restrict__ p2_w,  const float* __restrict__ p2_b,
        const float* __restrict__ fc2_w, const float* __restrict__ fc2_b,
        const float* __restrict__ eps,   float* __restrict__ out)
{
    extern __shared__ float sm[];
    float* emb_s = sm + OFF_EMB;
    float* h1s   = sm + OFF_H1;
    float* h2s   = sm + OFF_H2;
    float* xes   = sm + OFF_XE;   // [36][32], row 35 stays zero
    float* zs    = sm + OFF_ZS;
    float* mus   = sm + OFF_MU;
    float* gzs   = sm + OFF_GZ;
    float* g1s   = sm + OFF_G1;
    float* hds   = sm + OFF_HD;

    const int tid = threadIdx.x;
    const int bg0 = blockIdx.x * BBLK;

    for (int i = tid; i < KV * EE; i += NTH) emb_s[i] = emb[i];
    for (int i = tid; i < LL * 32; i += NTH) { h1s[i] = 0.0f; h2s[i] = 0.0f; }
    for (int i = tid; i < 36 * 32; i += NTH) xes[i] = 0.0f;
    __syncthreads();

    const int jt  = tid >> 3;        // 0..99
    const int bt  = tid & 7;         // 0..7
    const int j0  = jt * 2;
    const int b0  = bt * 4;
    const int warpj = jt >> 2;       // 0..24
    const int jt4   = jt & 3;

    // =====================  ENCODER  =====================
    for (int t = 0; t < TT; t++) {
        for (int i = tid; i < EE * 32; i += NTH) {
            int k = i >> 5, b = i & 31;
            int tok = x[(size_t)(bg0 + b) * TT + t];
            xes[k * 32 + b] = emb_s[tok * EE + k];
        }
        __syncthreads();

        // ---- layer 0 ----
        ull ar[2][2], az[2][2], an[2][2], ah[2][2];
        #pragma unroll
        for (int jj = 0; jj < 2; jj++) {
            int j = j0 + jj;
            ull br = pack2(eb_ih0[j] + eb_hh0[j]);
            ull bz = pack2(eb_ih0[200 + j] + eb_hh0[200 + j]);
            ull bn = pack2(eb_ih0[400 + j]);
            ull bh = pack2(eb_hh0[400 + j]);
            ar[jj][0] = ar[jj][1] = br;
            az[jj][0] = az[jj][1] = bz;
            an[jj][0] = an[jj][1] = bn;
            ah[jj][0] = ah[jj][1] = bh;
        }
        gemm_part(xes, g_wih0, KP_X, ar, az, an, warpj, jt4, b0);
        gemm_part(h1s, g_whh0, KP_H, ar, az, ah, warpj, jt4, b0);
        __syncthreads();
        #pragma unroll
        for (int jj = 0; jj < 2; jj++)
            #pragma unroll
            for (int p = 0; p < 2; p++) {
                int idx = (j0 + jj) * 32 + b0 + p * 2;
                float rl = sigm(lo2(ar[jj][p])), rh = sigm(hi2(ar[jj][p]));
                float zl = sigm(lo2(az[jj][p])), zh = sigm(hi2(az[jj][p]));
                float nl = tanhf(fmaf(rl, lo2(ah[jj][p]), lo2(an[jj][p])));
                float nh = tanhf(fmaf(rh, hi2(ah[jj][p]), hi2(an[jj][p])));
                float h0l = h1s[idx], h0h = h1s[idx + 1];
                h1s[idx]     = (1.0f - zl) * nl + zl * h0l;
                h1s[idx + 1] = (1.0f - zh) * nh + zh * h0h;
            }
        __syncthreads();

        // ---- layer 1 ----
        #pragma unroll
        for (int jj = 0; jj < 2; jj++) {
            int j = j0 + jj;
            ull br = pack2(eb_ih1[j] + eb_hh1[j]);
            ull bz = pack2(eb_ih1[200 + j] + eb_hh1[200 + j]);
            ull bn = pack2(eb_ih1[400 + j]);
            ull bh = pack2(eb_hh1[400 + j]);
            ar[jj][0] = ar[jj][1] = br;
            az[jj][0] = az[jj][1] = bz;
            an[jj][0] = an[jj][1] = bn;
            ah[jj][0] = ah[jj][1] = bh;
        }
        gemm_part(h1s, g_wih1, KP_H, ar, az, an, warpj, jt4, b0);
        gemm_part(h2s, g_whh1, KP_H, ar, az, ah, warpj, jt4, b0);
        __syncthreads();
        #pragma unroll
        for (int jj = 0; jj < 2; jj++)
            #pragma unroll
            for (int p = 0; p < 2; p++) {
                int idx = (j0 + jj) * 32 + b0 + p * 2;
                float rl = sigm(lo2(ar[jj][p])), rh = sigm(hi2(ar[jj][p]));
                float zl = sigm(lo2(az[jj][p])), zh = sigm(hi2(az[jj][p]));
                float nl = tanhf(fmaf(rl, lo2(ah[jj][p]), lo2(an[jj][p])));
                float nh = tanhf(fmaf(rh, hi2(ah[jj][p]), hi2(an[jj][p])));
                float h0l = h2s[idx], h0h = h2s[idx + 1];
                h2s[idx]     = (1.0f - zl) * nl + zl * h0l;
                h2s[idx + 1] = (1.0f - zh) * nh + zh * h0h;
            }
        __syncthreads();
    }

    // =====================  HEADS  =====================
    {
        float am[2][4], al[2][4];
        #pragma unroll
        for (int jj = 0; jj < 2; jj++) {
            float bm = fc11_b[j0 + jj], bl = fc12_b[j0 + jj];
            #pragma unroll
            for (int bb = 0; bb < 4; bb++) { am[jj][bb] = bm; al[jj][bb] = bl; }
        }
        const float* w1 = fc11_w + j0 * LL;
        const float* w2 = fc12_w + j0 * LL;
        #pragma unroll 1
        for (int k = 0; k < LL; k += 2) {
            float4 u = *(const float4*)(h2s + k * 32 + b0);
            float4 w = *(const float4*)(h2s + (k + 1) * 32 + b0);
            float va[4] = {u.x, u.y, u.z, u.w};
            float vb[4] = {w.x, w.y, w.z, w.w};
            #pragma unroll
            for (int jj = 0; jj < 2; jj++) {
                float2 a = *(const float2*)(w1 + jj * LL + k);
                float2 c = *(const float2*)(w2 + jj * LL + k);
                #pragma unroll
                for (int bb = 0; bb < 4; bb++) {
                    am[jj][bb] = fmaf(a.x, va[bb], am[jj][bb]);
                    am[jj][bb] = fmaf(a.y, vb[bb], am[jj][bb]);
                    al[jj][bb] = fmaf(c.x, va[bb], al[jj][bb]);
                    al[jj][bb] = fmaf(c.y, vb[bb], al[jj][bb]);
                }
            }
        }
        #pragma unroll
        for (int jj = 0; jj < 2; jj++)
            #pragma unroll
            for (int bb = 0; bb < 4; bb++) {
                int j = j0 + jj, b = b0 + bb, bg = bg0 + b;
                float m = am[jj][bb], lv = al[jj][bb];
                out[MU_OFF + (size_t)bg * LL + j] = m;
                out[LV_OFF + (size_t)bg * LL + j] = lv;
                mus[j * 32 + b] = m;
                zs[j * 32 + b] = fmaf(eps[(size_t)bg * LL + j], expf(0.5f * lv), m);
            }
        __syncthreads();
    }
    {
        float aa[2][4];
        #pragma unroll
        for (int jj = 0; jj < 2; jj++) {
            float bv = p1_b[j0 + jj];
            #pragma unroll
            for (int bb = 0; bb < 4; bb++) aa[jj][bb] = bv;
        }
        const float* w1 = p1_w + j0 * LL;
        #pragma unroll 1
        for (int k = 0; k < LL; k += 2) {
            float4 u = *(const float4*)(mus + k * 32 + b0);
            float4 w = *(const float4*)(mus + (k + 1) * 32 + b0);
            float va[4] = {u.x, u.y, u.z, u.w};
            float vb[4] = {w.x, w.y, w.z, w.w};
            #pragma unroll
            for (int jj = 0; jj < 2; jj++) {
                float2 a = *(const float2*)(w1 + jj * LL + k);
                #pragma unroll
                for (int bb = 0; bb < 4; bb++) {
                    aa[jj][bb] = fmaf(a.x, va[bb], aa[jj][bb]);
                    aa[jj][bb] = fmaf(a.y, vb[bb], aa[jj][bb]);
                }
            }
        }
        #pragma unroll
        for (int jj = 0; jj < 2; jj++)
            #pragma unroll
            for (int bb = 0; bb < 4; bb++)
                h2s[(j0 + jj) * 32 + b0 + bb] = fmaxf(aa[jj][bb], 0.0f);
        __syncthreads();
    }
    if (tid < 32) {
        float a = p2_b[0];
        for (int j = 0; j < LL; j++) a = fmaf(p2_w[j], h2s[j * 32 + tid], a);
        out[PY_OFF + bg0 + tid] = a;
    }
    for (int idx = tid; idx < GE3 * 32; idx += NTH) {
        int g = idx >> 5, b = idx & 31;
        float a = db_ih0[g];
        const float* w = dW_ih0 + g * LE;
        #pragma unroll 4
        for (int k = 0; k < LL; k++) a = fmaf(zs[k * 32 + b], w[k], a);
        gzs[idx] = a;
    }
    for (int i = tid; i < EE * 32; i += NTH) xes[i] = 0.0f;
    __syncthreads();

    // =====================  DECODER  =====================
    for (int t = 0; t < TT; t++) {
        for (int idx = tid; idx < GE3 * 32; idx += NTH) {
            int g = idx >> 5, b = idx & 31;
            float a = gzs[idx];
            const float* w = dW_ih0 + g * LE + LL;
            #pragma unroll 5
            for (int k = 0; k < EE; k++) a = fmaf(xes[k * 32 + b], w[k], a);
            g1s[idx] = a;
        }
        __syncthreads();
        for (int idx = tid; idx < EE * 32; idx += NTH) {
            int e = idx >> 5, b = idx & 31;
            float r  = sigm(g1s[e * 32 + b] + db_hh0[e]);
            float zg = sigm(g1s[(EE + e) * 32 + b] + db_hh0[EE + e]);
            float n  = tanhf(fmaf(r, db_hh0[2 * EE + e], g1s[(2 * EE + e) * 32 + b]));
            hds[idx] = (1.0f - zg) * n;
        }
        __syncthreads();
        for (int idx = tid; idx < GE3 * 32; idx += NTH) {
            int g = idx >> 5, b = idx & 31;
            float a = db_ih1[g];
            const float* w = dW_ih1 + g * EE;
            #pragma unroll 5
            for (int k = 0; k < EE; k++) a = fmaf(hds[k * 32 + b], w[k], a);
            g1s[idx] = a;
        }
        __syncthreads();
        for (int idx = tid; idx < EE * 32; idx += NTH) {
            int e = idx >> 5, b = idx & 31;
            float r  = sigm(g1s[e * 32 + b] + db_hh1[e]);
            float zg = sigm(g1s[(EE + e) * 32 + b] + db_hh1[EE + e]);
            float n  = tanhf(fmaf(r, db_hh1[2 * EE + e], g1s[(2 * EE + e) * 32 + b]));
            xes[idx] = (1.0f - zg) * n;
        }
        __syncthreads();
        for (int idx = tid; idx < KV * 32; idx += NTH) {
            int kk = idx >> 5, b = idx & 31;
            float a = fc2_b[kk];
            const float* w = fc2_w + kk * EE;
            #pragma unroll 5
            for (int e = 0; e < EE; e++) a = fmaf(xes[e * 32 + b], w[e], a);
            out[PRED_OFF + ((size_t)(bg0 + b) * TT + t) * KV + kk] = a;
        }
        __syncthreads();
    }
}

extern "C" void kernel_launch(void* const* d_in, const int* in_sizes, int n_in,
                              void* d_out, int out_size) {
    (void)in_sizes; (void)n_in; (void)out_size;
    const int*   x       = (const int*)  d_in[0];
    const float* emb     = (const float*)d_in[1];
    const float* eW_ih0  = (const float*)d_in[2];
    const float* eW_hh0  = (const float*)d_in[3];
    const float* eb_ih0  = (const float*)d_in[4];
    const float* eb_hh0  = (const float*)d_in[5];
    const float* eW_ih1  = (const float*)d_in[6];
    const float* eW_hh1  = (const float*)d_in[7];
    const float* eb_ih1  = (const float*)d_in[8];
    const float* eb_hh1  = (const float*)d_in[9];
    const float* dW_ih0  = (const float*)d_in[10];
    const float* db_ih0  = (const float*)d_in[12];
    const float* db_hh0  = (const float*)d_in[13];
    const float* dW_ih1  = (const float*)d_in[14];
    const float* db_ih1  = (const float*)d_in[16];
    const float* db_hh1  = (const float*)d_in[17];
    const float* fc11_w  = (const float*)d_in[18];
    const float* fc11_b  = (const float*)d_in[19];
    const float* fc12_w  = (const float*)d_in[20];
    const float* fc12_b  = (const float*)d_in[21];
    const float* p1_w    = (const float*)d_in[22];
    const float* p1_b    = (const float*)d_in[23];
    const float* p2_w    = (const float*)d_in[24];
    const float* p2_b    = (const float*)d_in[25];
    const float* fc2_w   = (const float*)d_in[26];
    const float* fc2_b   = (const float*)d_in[27];
    const float* eps     = (const float*)d_in[28];

    // weight permutation (cheap, per launch, graph-capturable)
    {
        int totH = 25 * 3 * 2 * KP_H * 4;
        int totX = 25 * 3 * 2 * KP_X * 4;
        pack_weights<<<(totX + 255) / 256, 256>>>(eW_ih0, 0, EE, KP_X);
        pack_weights<<<(totH + 255) / 256, 256>>>(eW_hh0, 1, LL, KP_H);
        pack_weights<<<(totH + 255) / 256, 256>>>(eW_ih1, 2, LL, KP_H);
        pack_weights<<<(totH + 255) / 256, 256>>>(eW_hh1, 3, LL, KP_H);
    }

    cudaFuncSetAttribute((const void*)vae_all,
                         cudaFuncAttributeMaxDynamicSharedMemorySize,
                         SMEM_FLOATS * (int)sizeof(float));

    vae_all<<<NCTA, NTH, SMEM_FLOATS * sizeof(float)>>>(
        x, emb, eb_ih0, eb_hh0, eb_ih1, eb_hh1,
        dW_ih0, db_ih0, db_hh0, dW_ih1, db_ih1, db_hh1,
        fc11_w, fc11_b, fc12_w, fc12_b, p1_w, p1_b, p2_w, p2_b,
        fc2_w, fc2_b, eps, (float*)d_out);
}

// round 3
// speedup vs baseline: 1.4663x; 1.4663x over previous
#include <cuda_runtime.h>
#include <math.h>

// Problem dims
#define NB 4096
#define TT 128
#define KV 64
#define EE 35
#define LL 200
#define GE3 105
#define LE 235

#define NTH 800   // 100 jt-groups x 8 bt
#define BBLK 32
#define NCTA (NB / BBLK)   // 128

#define KQ_H 50   // k-quads for K=200 matrices
#define KQ_X 9    // k-quads for K=35 (padded to 36)

// Output layout: concat(pred[B,T,K], mu[B,L], logvar[B,L], predY[B,1])
#define PRED_OFF ((size_t)0)
#define MU_OFF   ((size_t)NB * TT * KV)
#define LV_OFF   (MU_OFF + (size_t)NB * LL)
#define PY_OFF   (LV_OFF + (size_t)NB * LL)

// Packed weights: float4 index = (((warpj*3+gate)*2+jj)*KQ + kq)*4 + jt4
// Each float4 holds (w_k, w_k+1, w_k+2, w_k+3) for output row j=(warpj*4+jt4)*2+jj.
// One warp LDG.128 covers 4 consecutive float4s = 64B -> 1 L1 wavefront.
__device__ float4 g_wih0[25 * 3 * 2 * KQ_X * 4];   //  5400 float4
__device__ float4 g_whh0[25 * 3 * 2 * KQ_H * 4];   // 30000
__device__ float4 g_wih1[25 * 3 * 2 * KQ_H * 4];
__device__ float4 g_whh1[25 * 3 * 2 * KQ_H * 4];

// SMEM arena (floats)
#define OFF_EMB 0        // 2240
#define OFF_H1  2240     // 6400
#define OFF_H2  8640     // 6400
#define OFF_XE  15040    // 1152 (36 rows x 32, row 35 zero)
#define OFF_ZS  16192    // 6400
#define OFF_MU  22592    // 6400
#define OFF_GZ  28992    // 3360
#define OFF_G1  32352    // 3360
#define OFF_HD  35712    // 1120
#define OFF_TOK 36832    // 4096 (tokens [t][b] as float-reinterpreted ints)
#define SMEM_FLOATS 40928

__device__ __forceinline__ float sigm(float v) { return 1.0f / (1.0f + expf(-v)); }

// ---- prep: permute weights ----
__global__ void pack_weights(const float* __restrict__ src, int which, int K, int KQ) {
    float4* dst = (which == 0) ? g_wih0 : (which == 1) ? g_whh0
                : (which == 2) ? g_wih1 : g_whh1;
    int idx = blockIdx.x * blockDim.x + threadIdx.x;
    int total = 25 * 3 * 2 * KQ * 4;
    if (idx >= total) return;
    int jt4 = idx & 3;
    int r = idx >> 2;
    int kq = r % KQ; r /= KQ;
    int jj = r & 1;  r >>= 1;
    int gate = r % 3; r /= 3;
    int warpj = r;
    int j   = (warpj * 4 + jt4) * 2 + jj;
    int row = gate * LL + j;
    int k0 = kq * 4;
    float w[4];
    #pragma unroll
    for (int q = 0; q < 4; q++)
        w[q] = (k0 + q < K) ? src[row * K + k0 + q] : 0.0f;
    dst[idx] = make_float4(w[0], w[1], w[2], w[3]);
}

// acc (ar, az, ag)[jj][b] += W * acts over K. acts: SMEM [k][32].
__device__ __forceinline__ void gemm_part(const float* __restrict__ acts,
                                          const float4* __restrict__ wp, int KQ,
                                          float (&ar)[2][4], float (&az)[2][4], float (&ag)[2][4],
                                          int warpj, int jt4, int b0)
{
    const int base = warpj * 6 * KQ * 4 + jt4;  // float4 units
    #pragma unroll 2
    for (int kq = 0; kq < KQ; kq++) {
        float4 q0 = *(const float4*)(acts + (4 * kq + 0) * 32 + b0);
        float4 q1 = *(const float4*)(acts + (4 * kq + 1) * 32 + b0);
        float4 q2 = *(const float4*)(acts + (4 * kq + 2) * 32 + b0);
        float4 q3 = *(const float4*)(acts + (4 * kq + 3) * 32 + b0);
        float av[4][4] = {{q0.x, q0.y, q0.z, q0.w},
                          {q1.x, q1.y, q1.z, q1.w},
                          {q2.x, q2.y, q2.z, q2.w},
                          {q3.x, q3.y, q3.z, q3.w}};
        #pragma unroll
        for (int jj = 0; jj < 2; jj++) {
            float4 wr = wp[base + ((0 * 2 + jj) * KQ + kq) * 4];
            float wv[4] = {wr.x, wr.y, wr.z, wr.w};
            #pragma unroll
            for (int k = 0; k < 4; k++)
                #pragma unroll
                for (int b = 0; b < 4; b++)
                    ar[jj][b] = fmaf(wv[k], av[k][b], ar[jj][b]);
            float4 wz = wp[base + ((1 * 2 + jj) * KQ + kq) * 4];
            float zv[4] = {wz.x, wz.y, wz.z, wz.w};
            #pragma unroll
            for (int k = 0; k < 4; k++)
                #pragma unroll
                for (int b = 0; b < 4; b++)
                    az[jj][b] = fmaf(zv[k], av[k][b], az[jj][b]);
            float4 wn = wp[base + ((2 * 2 + jj) * KQ + kq) * 4];
            float nv[4] = {wn.x, wn.y, wn.z, wn.w};
            #pragma unroll
            for (int k = 0; k < 4; k++)
                #pragma unroll
                for (int b = 0; b < 4; b++)
                    ag[jj][b] = fmaf(nv[k], av[k][b], ag[jj][b]);
        }
    }
}

extern "C" __global__ void __launch_bounds__(NTH, 1)
vae_all(const int* __restrict__ x, const float* __restrict__ emb,
        const float* __restrict__ eb_ih0, const float* __restrict__ eb_hh0,
        const float* __restrict__ eb_ih1, const float* __restrict__ eb_hh1,
        const float* __restrict__ dW_ih0, const float* __restrict__ db_ih0,
        const float* __restrict__ db_hh0,
        const float* __restrict__ dW_ih1, const float* __restrict__ db_ih1,
        const float* __restrict__ db_hh1,
        const float* __restrict__ fc11_w, const float* __restrict__ fc11_b,
        const float* __restrict__ fc12_w, const float* __restrict__ fc12_b,
        const float* __restrict__ p1_w,  const float* __restrict__ p1_b,
        const float* __restrict__ p2_w,  const float* __restrict__ p2_b,
        const float* __restrict__ fc2_w, const float* __restrict__ fc2_b,
        const float* __restrict__ eps,   float* __restrict__ out)
{
    extern __shared__ float sm[];
    float* emb_s = sm + OFF_EMB;
    float* h1s   = sm + OFF_H1;
    float* h2s   = sm + OFF_H2;
    float* xes   = sm + OFF_XE;   // [36][32]
    float* zs    = sm + OFF_ZS;
    float* mus   = sm + OFF_MU;
    float* gzs   = sm + OFF_GZ;
    float* g1s   = sm + OFF_G1;
    float* hds   = sm + OFF_HD;
    int*   toks  = (int*)(sm + OFF_TOK);  // [t][b]

    const int tid = threadIdx.x;
    const int bg0 = blockIdx.x * BBLK;

    for (int i = tid; i < KV * EE; i += NTH) emb_s[i] = emb[i];
    for (int i = tid; i < LL * 32; i += NTH) { h1s[i] = 0.0f; h2s[i] = 0.0f; }
    for (int i = tid; i < 36 * 32; i += NTH) xes[i] = 0.0f;
    for (int i = tid; i < TT * 32; i += NTH) {
        int t = i >> 5, b = i & 31;
        toks[i] = x[(size_t)(bg0 + b) * TT + t];
    }
    __syncthreads();

    const int jt  = tid >> 3;        // 0..99
    const int bt  = tid & 7;         // 0..7
    const int j0  = jt * 2;
    const int b0  = bt * 4;
    const int warpj = jt >> 2;       // 0..24
    const int jt4   = jt & 3;

    // =====================  ENCODER  =====================
    for (int t = 0; t < TT; t++) {
        for (int i = tid; i < EE * 32; i += NTH) {
            int k = i >> 5, b = i & 31;
            xes[k * 32 + b] = emb_s[toks[t * 32 + b] * EE + k];
        }
        __syncthreads();

        // ---- layer 0 ----
        float ar[2][4], az[2][4], an[2][4], ah[2][4];
        #pragma unroll
        for (int jj = 0; jj < 2; jj++) {
            int j = j0 + jj;
            float br = eb_ih0[j] + eb_hh0[j];
            float bz = eb_ih0[200 + j] + eb_hh0[200 + j];
            float bn = eb_ih0[400 + j];
            float bh = eb_hh0[400 + j];
            #pragma unroll
            for (int b = 0; b < 4; b++) { ar[jj][b] = br; az[jj][b] = bz; an[jj][b] = bn; ah[jj][b] = bh; }
        }
        gemm_part(xes, g_wih0, KQ_X, ar, az, an, warpj, jt4, b0);
        gemm_part(h1s, g_whh0, KQ_H, ar, az, ah, warpj, jt4, b0);
        __syncthreads();
        #pragma unroll
        for (int jj = 0; jj < 2; jj++)
            #pragma unroll
            for (int b = 0; b < 4; b++) {
                int idx = (j0 + jj) * 32 + b0 + b;
                float ho = h1s[idx];
                float r  = sigm(ar[jj][b]);
                float zg = sigm(az[jj][b]);
                float n  = tanhf(fmaf(r, ah[jj][b], an[jj][b]));
                h1s[idx] = (1.0f - zg) * n + zg * ho;
            }
        __syncthreads();

        // ---- layer 1 ----
        #pragma unroll
        for (int jj = 0; jj < 2; jj++) {
            int j = j0 + jj;
            float br = eb_ih1[j] + eb_hh1[j];
            float bz = eb_ih1[200 + j] + eb_hh1[200 + j];
            float bn = eb_ih1[400 + j];
            float bh = eb_hh1[400 + j];
            #pragma unroll
            for (int b = 0; b < 4; b++) { ar[jj][b] = br; az[jj][b] = bz; an[jj][b] = bn; ah[jj][b] = bh; }
        }
        gemm_part(h1s, g_wih1, KQ_H, ar, az, an, warpj, jt4, b0);
        gemm_part(h2s, g_whh1, KQ_H, ar, az, ah, warpj, jt4, b0);
        __syncthreads();
        #pragma unroll
        for (int jj = 0; jj < 2; jj++)
            #pragma unroll
            for (int b = 0; b < 4; b++) {
                int idx = (j0 + jj) * 32 + b0 + b;
                float ho = h2s[idx];
                float r  = sigm(ar[jj][b]);
                float zg = sigm(az[jj][b]);
                float n  = tanhf(fmaf(r, ah[jj][b], an[jj][b]));
                h2s[idx] = (1.0f - zg) * n + zg * ho;
            }
        __syncthreads();
    }

    // =====================  HEADS  =====================
    {
        float am[2][4], al[2][4];
        #pragma unroll
        for (int jj = 0; jj < 2; jj++) {
            float bm = fc11_b[j0 + jj], bl = fc12_b[j0 + jj];
            #pragma unroll
            for (int b = 0; b < 4; b++) { am[jj][b] = bm; al[jj][b] = bl; }
        }
        const float* w1 = fc11_w + j0 * LL;
        const float* w2 = fc12_w + j0 * LL;
        #pragma unroll 1
        for (int k = 0; k < LL; k += 2) {
            float4 u = *(const float4*)(h2s + k * 32 + b0);
            float4 w = *(const float4*)(h2s + (k + 1) * 32 + b0);
            float va[4] = {u.x, u.y, u.z, u.w};
            float vb[4] = {w.x, w.y, w.z, w.w};
            #pragma unroll
            for (int jj = 0; jj < 2; jj++) {
                float2 a = *(const float2*)(w1 + jj * LL + k);
                float2 c = *(const float2*)(w2 + jj * LL + k);
                #pragma unroll
                for (int b = 0; b < 4; b++) {
                    am[jj][b] = fmaf(a.x, va[b], am[jj][b]);
                    am[jj][b] = fmaf(a.y, vb[b], am[jj][b]);
                    al[jj][b] = fmaf(c.x, va[b], al[jj][b]);
                    al[jj][b] = fmaf(c.y, vb[b], al[jj][b]);
                }
            }
        }
        #pragma unroll
        for (int jj = 0; jj < 2; jj++)
            #pragma unroll
            for (int b = 0; b < 4; b++) {
                int j = j0 + jj, bb = b0 + b, bg = bg0 + bb;
                float m = am[jj][b], lv = al[jj][b];
                out[MU_OFF + (size_t)bg * LL + j] = m;
                out[LV_OFF + (size_t)bg * LL + j] = lv;
                mus[j * 32 + bb] = m;
                zs[j * 32 + bb] = fmaf(eps[(size_t)bg * LL + j], expf(0.5f * lv), m);
            }
        __syncthreads();
    }
    {
        float aa[2][4];
        #pragma unroll
        for (int jj = 0; jj < 2; jj++) {
            float bv = p1_b[j0 + jj];
            #pragma unroll
            for (int b = 0; b < 4; b++) aa[jj][b] = bv;
        }
        const float* w1 = p1_w + j0 * LL;
        #pragma unroll 1
        for (int k = 0; k < LL; k += 2) {
            float4 u = *(const float4*)(mus + k * 32 + b0);
            float4 w = *(const float4*)(mus + (k + 1) * 32 + b0);
            float va[4] = {u.x, u.y, u.z, u.w};
            float vb[4] = {w.x, w.y, w.z, w.w};
            #pragma unroll
            for (int jj = 0; jj < 2; jj++) {
                float2 a = *(const float2*)(w1 + jj * LL + k);
                #pragma unroll
                for (int b = 0; b < 4; b++) {
                    aa[jj][b] = fmaf(a.x, va[b], aa[jj][b]);
                    aa[jj][b] = fmaf(a.y, vb[b], aa[jj][b]);
                }
            }
        }
        #pragma unroll
        for (int jj = 0; jj < 2; jj++)
            #pragma unroll
            for (int b = 0; b < 4; b++)
                h2s[(j0 + jj) * 32 + b0 + b] = fmaxf(aa[jj][b], 0.0f);
        __syncthreads();
    }
    if (tid < 32) {
        float a = p2_b[0];
        for (int j = 0; j < LL; j++) a = fmaf(p2_w[j], h2s[j * 32 + tid], a);
        out[PY_OFF + bg0 + tid] = a;
    }
    for (int idx = tid; idx < GE3 * 32; idx += NTH) {
        int g = idx >> 5, b = idx & 31;
        float a = db_ih0[g];
        const float* w = dW_ih0 + g * LE;
        #pragma unroll 4
        for (int k = 0; k < LL; k++) a = fmaf(zs[k * 32 + b], w[k], a);
        gzs[idx] = a;
    }
    for (int i = tid; i < EE * 32; i += NTH) xes[i] = 0.0f;
    __syncthreads();

    // =====================  DECODER  =====================
    for (int t = 0; t < TT; t++) {
        for (int idx = tid; idx < GE3 * 32; idx += NTH) {
            int g = idx >> 5, b = idx & 31;
            float a = gzs[idx];
            const float* w = dW_ih0 + g * LE + LL;
            #pragma unroll 5
            for (int k = 0; k < EE; k++) a = fmaf(xes[k * 32 + b], w[k], a);
            g1s[idx] = a;
        }
        __syncthreads();
        for (int idx = tid; idx < EE * 32; idx += NTH) {
            int e = idx >> 5, b = idx & 31;
            float r  = sigm(g1s[e * 32 + b] + db_hh0[e]);
            float zg = sigm(g1s[(EE + e) * 32 + b] + db_hh0[EE + e]);
            float n  = tanhf(fmaf(r, db_hh0[2 * EE + e], g1s[(2 * EE + e) * 32 + b]));
            hds[idx] = (1.0f - zg) * n;
        }
        __syncthreads();
        for (int idx = tid; idx < GE3 * 32; idx += NTH) {
            int g = idx >> 5, b = idx & 31;
            float a = db_ih1[g];
            const float* w = dW_ih1 + g * EE;
            #pragma unroll 5
            for (int k = 0; k < EE; k++) a = fmaf(hds[k * 32 + b], w[k], a);
            g1s[idx] = a;
        }
        __syncthreads();
        for (int idx = tid; idx < EE * 32; idx += NTH) {
            int e = idx >> 5, b = idx & 31;
            float r  = sigm(g1s[e * 32 + b] + db_hh1[e]);
            float zg = sigm(g1s[(EE + e) * 32 + b] + db_hh1[EE + e]);
            float n  = tanhf(fmaf(r, db_hh1[2 * EE + e], g1s[(2 * EE + e) * 32 + b]));
            xes[idx] = (1.0f - zg) * n;
        }
        __syncthreads();
        for (int idx = tid; idx < KV * 32; idx += NTH) {
            int kk = idx >> 5, b = idx & 31;
            float a = fc2_b[kk];
            const float* w = fc2_w + kk * EE;
            #pragma unroll 5
            for (int e = 0; e < EE; e++) a = fmaf(xes[e * 32 + b], w[e], a);
            out[PRED_OFF + ((size_t)(bg0 + b) * TT + t) * KV + kk] = a;
        }
        __syncthreads();
    }
}

extern "C" void kernel_launch(void* const* d_in, const int* in_sizes, int n_in,
                              void* d_out, int out_size) {
    (void)in_sizes; (void)n_in; (void)out_size;
    const int*   x       = (const int*)  d_in[0];
    const float* emb     = (const float*)d_in[1];
    const float* eW_ih0  = (const float*)d_in[2];
    const float* eW_hh0  = (const float*)d_in[3];
    const float* eb_ih0  = (const float*)d_in[4];
    const float* eb_hh0  = (const float*)d_in[5];
    const float* eW_ih1  = (const float*)d_in[6];
    const float* eW_hh1  = (const float*)d_in[7];
    const float* eb_ih1  = (const float*)d_in[8];
    const float* eb_hh1  = (const float*)d_in[9];
    const float* dW_ih0  = (const float*)d_in[10];
    const float* db_ih0  = (const float*)d_in[12];
    const float* db_hh0  = (const float*)d_in[13];
    const float* dW_ih1  = (const float*)d_in[14];
    const float* db_ih1  = (const float*)d_in[16];
    const float* db_hh1  = (const float*)d_in[17];
    const float* fc11_w  = (const float*)d_in[18];
    const float* fc11_b  = (const float*)d_in[19];
    const float* fc12_w  = (const float*)d_in[20];
    const float* fc12_b  = (const float*)d_in[21];
    const float* p1_w    = (const float*)d_in[22];
    const float* p1_b    = (const float*)d_in[23];
    const float* p2_w    = (const float*)d_in[24];
    const float* p2_b    = (const float*)d_in[25];
    const float* fc2_w   = (const float*)d_in[26];
    const float* fc2_b   = (const float*)d_in[27];
    const float* eps     = (const float*)d_in[28];

    {
        int totH = 25 * 3 * 2 * KQ_H * 4;
        int totX = 25 * 3 * 2 * KQ_X * 4;
        pack_weights<<<(totX + 255) / 256, 256>>>(eW_ih0, 0, EE, KQ_X);
        pack_weights<<<(totH + 255) / 256, 256>>>(eW_hh0, 1, LL, KQ_H);
        pack_weights<<<(totH + 255) / 256, 256>>>(eW_ih1, 2, LL, KQ_H);
        pack_weights<<<(totH + 255) / 256, 256>>>(eW_hh1, 3, LL, KQ_H);
    }

    cudaFuncSetAttribute((const void*)vae_all,
                         cudaFuncAttributeMaxDynamicSharedMemorySize,
                         SMEM_FLOATS * (int)sizeof(float));

    vae_all<<<NCTA, NTH, SMEM_FLOATS * sizeof(float)>>>(
        x, emb, eb_ih0, eb_hh0, eb_ih1, eb_hh1,
        dW_ih0, db_ih0, db_hh0, dW_ih1, db_ih1, db_hh1,
        fc11_w, fc11_b, fc12_w, fc12_b, p1_w, p1_b, p2_w, p2_b,
        fc2_w, fc2_b, eps, (float*)d_out);
}

// round 4
// speedup vs baseline: 1.5339x; 1.0461x over previous
#include <cuda_runtime.h>
#include <math.h>

typedef unsigned long long ull;

// Problem dims
#define NB 4096
#define TT 128
#define KV 64
#define EE 35
#define LL 200
#define GE3 105
#define LE 235

#define NTH 800   // 100 jt-groups x 8 bt
#define BBLK 32
#define NCTA (NB / BBLK)   // 128

#define KQ_H 50   // k-quads for K=200 matrices
#define KQ_X 9    // k-quads for K=35 (padded to 36)

// Output layout: concat(pred[B,T,K], mu[B,L], logvar[B,L], predY[B,1])
#define PRED_OFF ((size_t)0)
#define MU_OFF   ((size_t)NB * TT * KV)
#define LV_OFF   (MU_OFF + (size_t)NB * LL)
#define PY_OFF   (LV_OFF + (size_t)NB * LL)

// Packed weights: float4 index = (((warpj*3+gate)*2+jj)*KQ + kq)*4 + jt4
// float4 holds (w_k..w_k+3) for output row j=(warpj*4+jt4)*2+jj.
__device__ float4 g_wih0[25 * 3 * 2 * KQ_X * 4];
__device__ float4 g_whh0[25 * 3 * 2 * KQ_H * 4];
__device__ float4 g_wih1[25 * 3 * 2 * KQ_H * 4];
__device__ float4 g_whh1[25 * 3 * 2 * KQ_H * 4];

// SMEM arena (floats)
#define OFF_EMB   0        // 2240
#define OFF_H1    2240     // 6400
#define OFF_H2    8640     // 6400
#define OFF_XE    15040    // 1152 (36 rows x 32, row 35 zero)
#define OFF_ZS    16192    // 6400
#define OFF_MU    22592    // 6400
#define OFF_GZ    28992    // 3360
#define OFF_G1    32352    // 3360
#define OFF_HD    35712    // 1120
#define OFF_TOK   36832    // 4096
#define OFF_STASH 40928    // 6400 (800 threads x 8 floats, per-thread private)
#define SMEM_FLOATS 47328  // 189312 bytes

__device__ __forceinline__ float sigm(float v) { return 1.0f / (1.0f + expf(-v)); }

__device__ __forceinline__ ull ffma2(ull a, ull b, ull c) {
    ull d;
    asm("fma.rn.f32x2 %0, %1, %2, %3;" : "=l"(d) : "l"(a), "l"(b), "l"(c));
    return d;
}
__device__ __forceinline__ ull dup2(float f) {
    ull d; unsigned u = __float_as_uint(f);
    asm("mov.b64 %0, {%1, %1};" : "=l"(d) : "r"(u));
    return d;
}
__device__ __forceinline__ ull pack2(float f) { return dup2(f); }
__device__ __forceinline__ float lo2(ull v) { return __uint_as_float((unsigned)v); }
__device__ __forceinline__ float hi2(ull v) { return __uint_as_float((unsigned)(v >> 32)); }

// ---- prep: permute all 4 weight matrices in ONE launch (blockIdx.y selects) ----
__global__ void pack_all(const float* __restrict__ s0, const float* __restrict__ s1,
                         const float* __restrict__ s2, const float* __restrict__ s3) {
    int m = blockIdx.y;
    const float* src = (m == 0) ? s0 : (m == 1) ? s1 : (m == 2) ? s2 : s3;
    float4* dst = (m == 0) ? g_wih0 : (m == 1) ? g_whh0 : (m == 2) ? g_wih1 : g_whh1;
    int K  = (m == 0) ? EE : LL;
    int KQ = (m == 0) ? KQ_X : KQ_H;
    int idx = blockIdx.x * blockDim.x + threadIdx.x;
    int total = 25 * 3 * 2 * KQ * 4;
    if (idx >= total) return;
    int jt4 = idx & 3;
    int r = idx >> 2;
    int kq = r % KQ; r /= KQ;
    int jj = r & 1;  r >>= 1;
    int gate = r % 3; r /= 3;
    int warpj = r;
    int j   = (warpj * 4 + jt4) * 2 + jj;
    int row = gate * LL + j;
    int k0 = kq * 4;
    float w[4];
    #pragma unroll
    for (int q = 0; q < 4; q++)
        w[q] = (k0 + q < K) ? src[row * K + k0 + q] : 0.0f;
    dst[idx] = make_float4(w[0], w[1], w[2], w[3]);
}

__device__ __forceinline__ void acc8(ull (&acc)[2], float4 w,
                                     ulonglong2 A0, ulonglong2 A1,
                                     ulonglong2 A2, ulonglong2 A3) {
    ull w0 = dup2(w.x), w1 = dup2(w.y), w2 = dup2(w.z), w3 = dup2(w.w);
    acc[0] = ffma2(w0, A0.x, acc[0]);  acc[1] = ffma2(w0, A0.y, acc[1]);
    acc[0] = ffma2(w1, A1.x, acc[0]);  acc[1] = ffma2(w1, A1.y, acc[1]);
    acc[0] = ffma2(w2, A2.x, acc[0]);  acc[1] = ffma2(w2, A2.y, acc[1]);
    acc[0] = ffma2(w3, A3.x, acc[0]);  acc[1] = ffma2(w3, A3.y, acc[1]);
}

// acc (ar, az, a3)[jj][bpair] += W * acts over K, packed fp32x2 over batch pairs.
__device__ __forceinline__ void gemm_f2(const float* __restrict__ acts,
                                        const float4* __restrict__ wp, int KQ,
                                        ull (&ar)[2][2], ull (&az)[2][2], ull (&a3)[2][2],
                                        int warpj, int jt4, int b0)
{
    const int base = warpj * 6 * KQ * 4 + jt4;
    #pragma unroll 1
    for (int kq = 0; kq < KQ; kq++) {
        ulonglong2 A0 = *(const ulonglong2*)(acts + (4 * kq + 0) * 32 + b0);
        ulonglong2 A1 = *(const ulonglong2*)(acts + (4 * kq + 1) * 32 + b0);
        ulonglong2 A2 = *(const ulonglong2*)(acts + (4 * kq + 2) * 32 + b0);
        ulonglong2 A3 = *(const ulonglong2*)(acts + (4 * kq + 3) * 32 + b0);
        float4 wr0 = wp[base + ((0 + 0) * KQ + kq) * 4];
        float4 wr1 = wp[base + ((0 + 1) * KQ + kq) * 4];
        float4 wz0 = wp[base + ((2 + 0) * KQ + kq) * 4];
        float4 wz1 = wp[base + ((2 + 1) * KQ + kq) * 4];
        float4 wn0 = wp[base + ((4 + 0) * KQ + kq) * 4];
        float4 wn1 = wp[base + ((4 + 1) * KQ + kq) * 4];
        acc8(ar[0], wr0, A0, A1, A2, A3);
        acc8(ar[1], wr1, A0, A1, A2, A3);
        acc8(az[0], wz0, A0, A1, A2, A3);
        acc8(az[1], wz1, A0, A1, A2, A3);
        acc8(a3[0], wn0, A0, A1, A2, A3);
        acc8(a3[1], wn1, A0, A1, A2, A3);
    }
}

extern "C" __global__ void __launch_bounds__(NTH, 1)
vae_all(const int* __restrict__ x, const float* __restrict__ emb,
        const float* __restrict__ eb_ih0, const float* __restrict__ eb_hh0,
        const float* __restrict__ eb_ih1, const float* __restrict__ eb_hh1,
        const float* __restrict__ dW_ih0, const float* __restrict__ db_ih0,
        const float* __restrict__ db_hh0,
        const float* __restrict__ dW_ih1, const float* __restrict__ db_ih1,
        const float* __restrict__ db_hh1,
        const float* __restrict__ fc11_w, const float* __restrict__ fc11_b,
        const float* __restrict__ fc12_w, const float* __restrict__ fc12_b,
        const float* __restrict__ p1_w,  const float* __restrict__ p1_b,
        const float* __restrict__ p2_w,  const float* __restrict__ p2_b,
        const float* __restrict__ fc2_w, const float* __restrict__ fc2_b,
        const float* __restrict__ eps,   float* __restrict__ out)
{
    extern __shared__ float sm[];
    float* emb_s = sm + OFF_EMB;
    float* h1s   = sm + OFF_H1;
    float* h2s   = sm + OFF_H2;
    float* xes   = sm + OFF_XE;
    float* zs    = sm + OFF_ZS;
    float* mus   = sm + OFF_MU;
    float* gzs   = sm + OFF_GZ;
    float* g1s   = sm + OFF_G1;
    float* hds   = sm + OFF_HD;
    int*   toks  = (int*)(sm + OFF_TOK);
    float* stash = sm + OFF_STASH;

    const int tid = threadIdx.x;
    const int bg0 = blockIdx.x * BBLK;

    for (int i = tid; i < KV * EE; i += NTH) emb_s[i] = emb[i];
    for (int i = tid; i < LL * 32; i += NTH) { h1s[i] = 0.0f; h2s[i] = 0.0f; }
    for (int i = tid; i < 36 * 32; i += NTH) xes[i] = 0.0f;
    for (int i = tid; i < TT * 32; i += NTH) {
        int t = i >> 5, b = i & 31;
        toks[i] = x[(size_t)(bg0 + b) * TT + t];
    }
    __syncthreads();

    const int jt  = tid >> 3;        // 0..99
    const int bt  = tid & 7;         // 0..7
    const int j0  = jt * 2;
    const int b0  = bt * 4;
    const int warpj = jt >> 2;
    const int jt4   = jt & 3;
    ulonglong2* mystash = (ulonglong2*)(stash + tid * 8);

    // =====================  ENCODER  =====================
    for (int t = 0; t < TT; t++) {
        for (int i = tid; i < EE * 32; i += NTH) {
            int k = i >> 5, b = i & 31;
            xes[k * 32 + b] = emb_s[toks[t * 32 + b] * EE + k];
        }
        __syncthreads();

        // ---- layer 0 ----
        ull ar[2][2], az[2][2], at[2][2];
        #pragma unroll
        for (int jj = 0; jj < 2; jj++) {
            int j = j0 + jj;
            ar[jj][0] = ar[jj][1] = pack2(eb_ih0[j] + eb_hh0[j]);
            az[jj][0] = az[jj][1] = pack2(eb_ih0[200 + j] + eb_hh0[200 + j]);
            at[jj][0] = at[jj][1] = pack2(eb_ih0[400 + j]);
        }
        gemm_f2(xes, g_wih0, KQ_X, ar, az, at, warpj, jt4, b0);
        mystash[0] = make_ulonglong2(at[0][0], at[0][1]);
        mystash[1] = make_ulonglong2(at[1][0], at[1][1]);
        #pragma unroll
        for (int jj = 0; jj < 2; jj++)
            at[jj][0] = at[jj][1] = pack2(eb_hh0[400 + j0 + jj]);
        gemm_f2(h1s, g_whh0, KQ_H, ar, az, at, warpj, jt4, b0);
        __syncthreads();
        {
            ulonglong2 s0 = mystash[0], s1 = mystash[1];
            ull an2[2][2] = {{s0.x, s0.y}, {s1.x, s1.y}};
            #pragma unroll
            for (int jj = 0; jj < 2; jj++)
                #pragma unroll
                for (int p = 0; p < 2; p++) {
                    int idx = (j0 + jj) * 32 + b0 + p * 2;
                    float rl = sigm(lo2(ar[jj][p])), rh = sigm(hi2(ar[jj][p]));
                    float zl = sigm(lo2(az[jj][p])), zh = sigm(hi2(az[jj][p]));
                    float nl = tanhf(fmaf(rl, lo2(at[jj][p]), lo2(an2[jj][p])));
                    float nh = tanhf(fmaf(rh, hi2(at[jj][p]), hi2(an2[jj][p])));
                    float h0l = h1s[idx], h0h = h1s[idx + 1];
                    h1s[idx]     = (1.0f - zl) * nl + zl * h0l;
                    h1s[idx + 1] = (1.0f - zh) * nh + zh * h0h;
                }
        }
        __syncthreads();

        // ---- layer 1 ----
        #pragma unroll
        for (int jj = 0; jj < 2; jj++) {
            int j = j0 + jj;
            ar[jj][0] = ar[jj][1] = pack2(eb_ih1[j] + eb_hh1[j]);
            az[jj][0] = az[jj][1] = pack2(eb_ih1[200 + j] + eb_hh1[200 + j]);
            at[jj][0] = at[jj][1] = pack2(eb_ih1[400 + j]);
        }
        gemm_f2(h1s, g_wih1, KQ_H, ar, az, at, warpj, jt4, b0);
        mystash[0] = make_ulonglong2(at[0][0], at[0][1]);
        mystash[1] = make_ulonglong2(at[1][0], at[1][1]);
        #pragma unroll
        for (int jj = 0; jj < 2; jj++)
            at[jj][0] = at[jj][1] = pack2(eb_hh1[400 + j0 + jj]);
        gemm_f2(h2s, g_whh1, KQ_H, ar, az, at, warpj, jt4, b0);
        __syncthreads();
        {
            ulonglong2 s0 = mystash[0], s1 = mystash[1];
            ull an2[2][2] = {{s0.x, s0.y}, {s1.x, s1.y}};
            #pragma unroll
            for (int jj = 0; jj < 2; jj++)
                #pragma unroll
                for (int p = 0; p < 2; p++) {
                    int idx = (j0 + jj) * 32 + b0 + p * 2;
                    float rl = sigm(lo2(ar[jj][p])), rh = sigm(hi2(ar[jj][p]));
                    float zl = sigm(lo2(az[jj][p])), zh = sigm(hi2(az[jj][p]));
                    float nl = tanhf(fmaf(rl, lo2(at[jj][p]), lo2(an2[jj][p])));
                    float nh = tanhf(fmaf(rh, hi2(at[jj][p]), hi2(an2[jj][p])));
                    float h0l = h2s[idx], h0h = h2s[idx + 1];
                    h2s[idx]     = (1.0f - zl) * nl + zl * h0l;
                    h2s[idx + 1] = (1.0f - zh) * nh + zh * h0h;
                }
        }
        __syncthreads();
    }

    // =====================  HEADS  =====================
    {
        float am[2][4], al[2][4];
        #pragma unroll
        for (int jj = 0; jj < 2; jj++) {
            float bm = fc11_b[j0 + jj], bl = fc12_b[j0 + jj];
            #pragma unroll
            for (int b = 0; b < 4; b++) { am[jj][b] = bm; al[jj][b] = bl; }
        }
        const float* w1 = fc11_w + j0 * LL;
        const float* w2 = fc12_w + j0 * LL;
        #pragma unroll 1
        for (int k = 0; k < LL; k += 2) {
            float4 u = *(const float4*)(h2s + k * 32 + b0);
            float4 w = *(const float4*)(h2s + (k + 1) * 32 + b0);
            float va[4] = {u.x, u.y, u.z, u.w};
            float vb[4] = {w.x, w.y, w.z, w.w};
            #pragma unroll
            for (int jj = 0; jj < 2; jj++) {
                float2 a = *(const float2*)(w1 + jj * LL + k);
                float2 c = *(const float2*)(w2 + jj * LL + k);
                #pragma unroll
                for (int b = 0; b < 4; b++) {
                    am[jj][b] = fmaf(a.x, va[b], am[jj][b]);
                    am[jj][b] = fmaf(a.y, vb[b], am[jj][b]);
                    al[jj][b] = fmaf(c.x, va[b], al[jj][b]);
                    al[jj][b] = fmaf(c.y, vb[b], al[jj][b]);
                }
            }
        }
        #pragma unroll
        for (int jj = 0; jj < 2; jj++)
            #pragma unroll
            for (int b = 0; b < 4; b++) {
                int j = j0 + jj, bb = b0 + b, bg = bg0 + bb;
                float m = am[jj][b], lv = al[jj][b];
                out[MU_OFF + (size_t)bg * LL + j] = m;
                out[LV_OFF + (size_t)bg * LL + j] = lv;
                mus[j * 32 + bb] = m;
                zs[j * 32 + bb] = fmaf(eps[(size_t)bg * LL + j], expf(0.5f * lv), m);
            }
        __syncthreads();
    }
    {
        float aa[2][4];
        #pragma unroll
        for (int jj = 0; jj < 2; jj++) {
            float bv = p1_b[j0 + jj];
            #pragma unroll
            for (int b = 0; b < 4; b++) aa[jj][b] = bv;
        }
        const float* w1 = p1_w + j0 * LL;
        #pragma unroll 1
        for (int k = 0; k < LL; k += 2) {
            float4 u = *(const float4*)(mus + k * 32 + b0);
            float4 w = *(const float4*)(mus + (k + 1) * 32 + b0);
            float va[4] = {u.x, u.y, u.z, u.w};
            float vb[4] = {w.x, w.y, w.z, w.w};
            #pragma unroll
            for (int jj = 0; jj < 2; jj++) {
                float2 a = *(const float2*)(w1 + jj * LL + k);
                #pragma unroll
                for (int b = 0; b < 4; b++) {
                    aa[jj][b] = fmaf(a.x, va[b], aa[jj][b]);
                    aa[jj][b] = fmaf(a.y, vb[b], aa[jj][b]);
                }
            }
        }
        #pragma unroll
        for (int jj = 0; jj < 2; jj++)
            #pragma unroll
            for (int b = 0; b < 4; b++)
                h2s[(j0 + jj) * 32 + b0 + b] = fmaxf(aa[jj][b], 0.0f);
        __syncthreads();
    }
    if (tid < 32) {
        float a = p2_b[0];
        for (int j = 0; j < LL; j++) a = fmaf(p2_w[j], h2s[j * 32 + tid], a);
        out[PY_OFF + bg0 + tid] = a;
    }
    for (int idx = tid; idx < GE3 * 32; idx += NTH) {
        int g = idx >> 5, b = idx & 31;
        float a = db_ih0[g];
        const float* w = dW_ih0 + g * LE;
        #pragma unroll 4
        for (int k = 0; k < LL; k++) a = fmaf(zs[k * 32 + b], w[k], a);
        gzs[idx] = a;
    }
    for (int i = tid; i < EE * 32; i += NTH) xes[i] = 0.0f;
    __syncthreads();

    // =====================  DECODER  =====================
    for (int t = 0; t < TT; t++) {
        for (int idx = tid; idx < GE3 * 32; idx += NTH) {
            int g = idx >> 5, b = idx & 31;
            float a = gzs[idx];
            const float* w = dW_ih0 + g * LE + LL;
            #pragma unroll 5
            for (int k = 0; k < EE; k++) a = fmaf(xes[k * 32 + b], w[k], a);
            g1s[idx] = a;
        }
        __syncthreads();
        for (int idx = tid; idx < EE * 32; idx += NTH) {
            int e = idx >> 5, b = idx & 31;
            float r  = sigm(g1s[e * 32 + b] + db_hh0[e]);
            float zg = sigm(g1s[(EE + e) * 32 + b] + db_hh0[EE + e]);
            float n  = tanhf(fmaf(r, db_hh0[2 * EE + e], g1s[(2 * EE + e) * 32 + b]));
            hds[idx] = (1.0f - zg) * n;
        }
        __syncthreads();
        for (int idx = tid; idx < GE3 * 32; idx += NTH) {
            int g = idx >> 5, b = idx & 31;
            float a = db_ih1[g];
            const float* w = dW_ih1 + g * EE;
            #pragma unroll 5
            for (int k = 0; k < EE; k++) a = fmaf(hds[k * 32 + b], w[k], a);
            g1s[idx] = a;
        }
        __syncthreads();
        for (int idx = tid; idx < EE * 32; idx += NTH) {
            int e = idx >> 5, b = idx & 31;
            float r  = sigm(g1s[e * 32 + b] + db_hh1[e]);
            float zg = sigm(g1s[(EE + e) * 32 + b] + db_hh1[EE + e]);
            float n  = tanhf(fmaf(r, db_hh1[2 * EE + e], g1s[(2 * EE + e) * 32 + b]));
            xes[idx] = (1.0f - zg) * n;
        }
        __syncthreads();
        for (int idx = tid; idx < KV * 32; idx += NTH) {
            int kk = idx >> 5, b = idx & 31;
            float a = fc2_b[kk];
            const float* w = fc2_w + kk * EE;
            #pragma unroll 5
            for (int e = 0; e < EE; e++) a = fmaf(xes[e * 32 + b], w[e], a);
            out[PRED_OFF + ((size_t)(bg0 + b) * TT + t) * KV + kk] = a;
        }
        __syncthreads();
    }
}

extern "C" void kernel_launch(void* const* d_in, const int* in_sizes, int n_in,
                              void* d_out, int out_size) {
    (void)in_sizes; (void)n_in; (void)out_size;
    const int*   x       = (const int*)  d_in[0];
    const float* emb     = (const float*)d_in[1];
    const float* eW_ih0  = (const float*)d_in[2];
    const float* eW_hh0  = (const float*)d_in[3];
    const float* eb_ih0  = (const float*)d_in[4];
    const float* eb_hh0  = (const float*)d_in[5];
    const float* eW_ih1  = (const float*)d_in[6];
    const float* eW_hh1  = (const float*)d_in[7];
    const float* eb_ih1  = (const float*)d_in[8];
    const float* eb_hh1  = (const float*)d_in[9];
    const float* dW_ih0  = (const float*)d_in[10];
    const float* db_ih0  = (const float*)d_in[12];
    const float* db_hh0  = (const float*)d_in[13];
    const float* dW_ih1  = (const float*)d_in[14];
    const float* db_ih1  = (const float*)d_in[16];
    const float* db_hh1  = (const float*)d_in[17];
    const float* fc11_w  = (const float*)d_in[18];
    const float* fc11_b  = (const float*)d_in[19];
    const float* fc12_w  = (const float*)d_in[20];
    const float* fc12_b  = (const float*)d_in[21];
    const float* p1_w    = (const float*)d_in[22];
    const float* p1_b    = (const float*)d_in[23];
    const float* p2_w    = (const float*)d_in[24];
    const float* p2_b    = (const float*)d_in[25];
    const float* fc2_w   = (const float*)d_in[26];
    const float* fc2_b   = (const float*)d_in[27];
    const float* eps     = (const float*)d_in[28];

    // Single pack launch (4 matrices via blockIdx.y) — keeps launch count low
    // so ncu -s 5 lands on vae_all.
    {
        int totH = 25 * 3 * 2 * KQ_H * 4;
        dim3 grid((totH + 255) / 256, 4);
        pack_all<<<grid, 256>>>(eW_ih0, eW_hh0, eW_ih1, eW_hh1);
    }

    cudaFuncSetAttribute((const void*)vae_all,
                         cudaFuncAttributeMaxDynamicSharedMemorySize,
                         SMEM_FLOATS * (int)sizeof(float));

    vae_all<<<NCTA, NTH, SMEM_FLOATS * sizeof(float)>>>(
        x, emb, eb_ih0, eb_hh0, eb_ih1, eb_hh1,
        dW_ih0, db_ih0, db_hh0, dW_ih1, db_ih1, db_hh1,
        fc11_w, fc11_b, fc12_w, fc12_b, p1_w, p1_b, p2_w, p2_b,
        fc2_w, fc2_b, eps, (float*)d_out);
}

// round 5
// speedup vs baseline: 3.3349x; 2.1742x over previous
#include <cuda_runtime.h>
#include <math.h>
#include <stdint.h>

// Problem dims
#define NB 4096
#define TT 128
#define KV 64
#define EE 35
#define LL 200
#define GE3 105
#define LE 235

#define NTH 800    // 25 warps
#define BBLK 32
#define NCTA (NB / BBLK)   // 128

// Output layout: concat(pred[B,T,K], mu[B,L], logvar[B,L], predY[B,1])
#define PRED_OFF ((size_t)0)
#define MU_OFF   ((size_t)NB * TT * KV)
#define LV_OFF   (MU_OFF + (size_t)NB * LL)
#define PY_OFF   (LV_OFF + (size_t)NB * LL)

// MMA geometry: m16n8k8 tf32. Per warp: 4 gate-tiles (r,z,in,hn), 2 m-tiles.
#define NK0IH 5    // K=35  -> 5 k8 (padded to 40)
#define NKH   25   // K=200 -> 25 k8
#define NTILES 75  // 600 rows / 8 per weight matrix

// Packed tf32 B-fragments: [tile(75)][k8(nk)][lane(32)] float2 (b0,b1)
__device__ uint2 g_b0ih[NTILES * NK0IH * 32];   // eW_ih0
__device__ uint2 g_b0hh[NTILES * NKH * 32];     // eW_hh0
__device__ uint2 g_b1ih[NTILES * NKH * 32];     // eW_ih1
__device__ uint2 g_b1hh[NTILES * NKH * 32];     // eW_hh1

// SMEM arena (floats)
#define APAD 36    // act row stride (bank-spread)
#define GPAD 33    // gate row stride
#define OFF_EMB 0                         // 2240  (KV*EE)
#define OFF_H1  2240                      // 7200  (200*36)
#define OFF_H2  (OFF_H1 + 200*APAD)      // 7200
#define OFF_XE  (OFF_H2 + 200*APAD)      // 1440  (40*36, rows 35..39 zero)
#define OFF_GSM (OFF_XE + 40*APAD)       // 28160 (gates 800*33 / decoder scratch)
#define GSM_SZ  28160
#define OFF_TOK (OFF_GSM + GSM_SZ)       // 4096
#define SMEM_FLOATS (OFF_TOK + TT*32)    // 50336 floats = 201344 B

__device__ __forceinline__ float sigm(float v) { return 1.0f / (1.0f + expf(-v)); }

__device__ __forceinline__ uint32_t to_tf32(float f) {
    uint32_t u;
    asm("cvt.rna.tf32.f32 %0, %1;" : "=r"(u) : "f"(f));
    return u;
}

__device__ __forceinline__ void mma8(float (&c)[4], const uint32_t (&a)[4], uint2 b) {
    asm volatile(
        "mma.sync.aligned.m16n8k8.row.col.f32.tf32.tf32.f32 "
        "{%0,%1,%2,%3}, {%4,%5,%6,%7}, {%8,%9}, {%0,%1,%2,%3};"
        : "+f"(c[0]), "+f"(c[1]), "+f"(c[2]), "+f"(c[3])
        : "r"(a[0]), "r"(a[1]), "r"(a[2]), "r"(a[3]), "r"(b.x), "r"(b.y));
}

// Load A-fragments (2 m-tiles) from acts[k][b] (stride APAD), convert to tf32.
__device__ __forceinline__ void lda(uint32_t (&a)[2][4], const float* __restrict__ acts,
                                    int k0, int gid, int tig) {
    const float* r0 = acts + (k0 + tig) * APAD;
    const float* r1 = acts + (k0 + tig + 4) * APAD;
    #pragma unroll
    for (int m = 0; m < 2; m++) {
        int b = m * 16 + gid;
        a[m][0] = to_tf32(r0[b]);
        a[m][1] = to_tf32(r0[b + 8]);
        a[m][2] = to_tf32(r1[b]);
        a[m][3] = to_tf32(r1[b + 8]);
    }
}

// Store one gate-tile's D-frags into gsm[n][b] (stride GPAD).
__device__ __forceinline__ void stfrag(float* __restrict__ gsm, int n0,
                                       const float (&c)[2][4], int gid, int tig) {
    #pragma unroll
    for (int m = 0; m < 2; m++) {
        int b = m * 16 + gid;
        gsm[(n0 + 2 * tig) * GPAD + b]         = c[m][0];
        gsm[(n0 + 2 * tig + 1) * GPAD + b]     = c[m][1];
        gsm[(n0 + 2 * tig) * GPAD + b + 8]     = c[m][2];
        gsm[(n0 + 2 * tig + 1) * GPAD + b + 8] = c[m][3];
    }
}

// ---- prep: pack weight matrices into tf32 B-fragment layout ----
__global__ void pack_b(const float* __restrict__ s0, const float* __restrict__ s1,
                       const float* __restrict__ s2, const float* __restrict__ s3) {
    int m = blockIdx.y;
    const float* src = (m == 0) ? s0 : (m == 1) ? s1 : (m == 2) ? s2 : s3;
    uint2* dst = (m == 0) ? g_b0ih : (m == 1) ? g_b0hh : (m == 2) ? g_b1ih : g_b1hh;
    int K  = (m == 0) ? EE : LL;
    int nk = (m == 0) ? NK0IH : NKH;
    int idx = blockIdx.x * blockDim.x + threadIdx.x;
    int total = NTILES * nk * 32;
    if (idx >= total) return;
    int lane = idx & 31;
    int r = idx >> 5;
    int k8 = r % nk;  r /= nk;
    int tile = r;
    int gid = lane >> 2, tig = lane & 3;
    int n = tile * 8 + gid;
    int k0 = k8 * 8;
    float w0 = (k0 + tig     < K) ? src[n * K + k0 + tig]     : 0.0f;
    float w1 = (k0 + tig + 4 < K) ? src[n * K + k0 + tig + 4] : 0.0f;
    uint2 o;
    asm("cvt.rna.tf32.f32 %0, %1;" : "=r"(o.x) : "f"(w0));
    asm("cvt.rna.tf32.f32 %0, %1;" : "=r"(o.y) : "f"(w1));
    dst[idx] = o;
}

extern "C" __global__ void __launch_bounds__(NTH, 1)
vae_all(const int* __restrict__ x, const float* __restrict__ emb,
        const float* __restrict__ eb_ih0, const float* __restrict__ eb_hh0,
        const float* __restrict__ eb_ih1, const float* __restrict__ eb_hh1,
        const float* __restrict__ dW_ih0, const float* __restrict__ db_ih0,
        const float* __restrict__ db_hh0,
        const float* __restrict__ dW_ih1, const float* __restrict__ db_ih1,
        const float* __restrict__ db_hh1,
        const float* __restrict__ fc11_w, const float* __restrict__ fc11_b,
        const float* __restrict__ fc12_w, const float* __restrict__ fc12_b,
        const float* __restrict__ p1_w,  const float* __restrict__ p1_b,
        const float* __restrict__ p2_w,  const float* __restrict__ p2_b,
        const float* __restrict__ fc2_w, const float* __restrict__ fc2_b,
        const float* __restrict__ eps,   float* __restrict__ out)
{
    extern __shared__ float sm[];
    float* emb_s = sm + OFF_EMB;
    float* h1s   = sm + OFF_H1;    // [200][APAD]
    float* h2s   = sm + OFF_H2;    // [200][APAD]
    float* xes   = sm + OFF_XE;    // [40][APAD]
    float* gsm   = sm + OFF_GSM;   // encoder: [800][GPAD]; later decoder scratch
    int*   toks  = (int*)(sm + OFF_TOK);

    const int tid = threadIdx.x;
    const int bg0 = blockIdx.x * BBLK;

    for (int i = tid; i < KV * EE; i += NTH) emb_s[i] = emb[i];
    for (int i = tid; i < 200 * APAD; i += NTH) { h1s[i] = 0.0f; h2s[i] = 0.0f; }
    for (int i = tid; i < 40 * APAD; i += NTH) xes[i] = 0.0f;
    for (int i = tid; i < TT * 32; i += NTH) {
        int t = i >> 5, b = i & 31;
        toks[i] = x[(size_t)(bg0 + b) * TT + t];
    }
    __syncthreads();

    const int lane = tid & 31;
    const int wrp  = tid >> 5;     // 0..24
    const int gid  = lane >> 2;
    const int tig  = lane & 3;

    // elementwise-phase mapping
    const int jt = tid >> 3;       // 0..99
    const int j0 = jt * 2;
    const int b0 = (tid & 7) * 4;

    // =====================  ENCODER (tf32 tensor cores)  =====================
    for (int t = 0; t < TT; t++) {
        for (int i = tid; i < EE * 32; i += NTH) {
            int k = i >> 5, b = i & 31;
            xes[k * APAD + b] = emb_s[toks[t * 32 + b] * EE + k];
        }
        __syncthreads();

        #pragma unroll 1
        for (int layer = 0; layer < 2; layer++) {
            const float* Aih = (layer == 0) ? xes : h1s;
            const float* Ahh = (layer == 0) ? h1s : h2s;
            float*       hb  = (layer == 0) ? h1s : h2s;
            const uint2* Bih = (layer == 0) ? g_b0ih : g_b1ih;
            const uint2* Bhh = (layer == 0) ? g_b0hh : g_b1hh;
            const int    nkih = (layer == 0) ? NK0IH : NKH;
            const float* bih = (layer == 0) ? eb_ih0 : eb_ih1;
            const float* bhh = (layer == 0) ? eb_hh0 : eb_hh1;

            float cr[2][4] = {}, cz[2][4] = {}, ci[2][4] = {}, ch[2][4] = {};

            // ih pass: gates r, z, in
            #pragma unroll 1
            for (int k8 = 0; k8 < nkih; k8++) {
                uint32_t a[2][4];
                lda(a, Aih, k8 * 8, gid, tig);
                uint2 br = Bih[(( 0 + wrp) * nkih + k8) * 32 + lane];
                uint2 bz = Bih[((25 + wrp) * nkih + k8) * 32 + lane];
                uint2 bn = Bih[((50 + wrp) * nkih + k8) * 32 + lane];
                #pragma unroll
                for (int m = 0; m < 2; m++) {
                    mma8(cr[m], a[m], br);
                    mma8(cz[m], a[m], bz);
                    mma8(ci[m], a[m], bn);
                }
            }
            // hh pass: gates r, z, hn
            #pragma unroll 1
            for (int k8 = 0; k8 < NKH; k8++) {
                uint32_t a[2][4];
                lda(a, Ahh, k8 * 8, gid, tig);
                uint2 br = Bhh[(( 0 + wrp) * NKH + k8) * 32 + lane];
                uint2 bz = Bhh[((25 + wrp) * NKH + k8) * 32 + lane];
                uint2 bn = Bhh[((50 + wrp) * NKH + k8) * 32 + lane];
                #pragma unroll
                for (int m = 0; m < 2; m++) {
                    mma8(cr[m], a[m], br);
                    mma8(cz[m], a[m], bz);
                    mma8(ch[m], a[m], bn);
                }
            }

            stfrag(gsm,   0 + 8 * wrp, cr, gid, tig);
            stfrag(gsm, 200 + 8 * wrp, cz, gid, tig);
            stfrag(gsm, 400 + 8 * wrp, ci, gid, tig);
            stfrag(gsm, 600 + 8 * wrp, ch, gid, tig);
            __syncthreads();

            // GRU elementwise update
            #pragma unroll
            for (int jj = 0; jj < 2; jj++) {
                int j = j0 + jj;
                float brj = bih[j] + bhh[j];
                float bzj = bih[200 + j] + bhh[200 + j];
                float bij = bih[400 + j];
                float bhj = bhh[400 + j];
                #pragma unroll
                for (int bb = 0; bb < 4; bb++) {
                    int b = b0 + bb;
                    float gr = gsm[j * GPAD + b] + brj;
                    float gz = gsm[(200 + j) * GPAD + b] + bzj;
                    float gi = gsm[(400 + j) * GPAD + b] + bij;
                    float gh = gsm[(600 + j) * GPAD + b] + bhj;
                    float r  = sigm(gr);
                    float zg = sigm(gz);
                    float n  = tanhf(fmaf(r, gh, gi));
                    float ho = hb[j * APAD + b];
                    hb[j * APAD + b] = (1.0f - zg) * n + zg * ho;
                }
            }
            __syncthreads();
        }
    }

    // decoder / heads scratch overlaid on gsm
    float* zs    = gsm;            // [200][32]
    float* mus   = gsm + 6400;     // [200][32]
    float* gzs   = gsm + 12800;    // [105][32]
    float* g1s   = gsm + 16160;    // [105][32]
    float* hds   = gsm + 19520;    // [35][32]
    float* lastw = gsm + 20640;    // [35][32]
    float* t1s   = gsm + 21760;    // [200][32]

    // =====================  HEADS  =====================
    {
        float am[2][4], al[2][4];
        #pragma unroll
        for (int jj = 0; jj < 2; jj++) {
            float bm = fc11_b[j0 + jj], bl = fc12_b[j0 + jj];
            #pragma unroll
            for (int b = 0; b < 4; b++) { am[jj][b] = bm; al[jj][b] = bl; }
        }
        const float* w1 = fc11_w + j0 * LL;
        const float* w2 = fc12_w + j0 * LL;
        #pragma unroll 1
        for (int k = 0; k < LL; k += 2) {
            float4 u = *(const float4*)(h2s + k * APAD + b0);
            float4 w = *(const float4*)(h2s + (k + 1) * APAD + b0);
            float va[4] = {u.x, u.y, u.z, u.w};
            float vb[4] = {w.x, w.y, w.z, w.w};
            #pragma unroll
            for (int jj = 0; jj < 2; jj++) {
                float2 a = *(const float2*)(w1 + jj * LL + k);
                float2 c = *(const float2*)(w2 + jj * LL + k);
                #pragma unroll
                for (int b = 0; b < 4; b++) {
                    am[jj][b] = fmaf(a.x, va[b], am[jj][b]);
                    am[jj][b] = fmaf(a.y, vb[b], am[jj][b]);
                    al[jj][b] = fmaf(c.x, va[b], al[jj][b]);
                    al[jj][b] = fmaf(c.y, vb[b], al[jj][b]);
                }
            }
        }
        __syncthreads();  // done reading gsm-era data? (gsm reused below)
        #pragma unroll
        for (int jj = 0; jj < 2; jj++)
            #pragma unroll
            for (int b = 0; b < 4; b++) {
                int j = j0 + jj, bb = b0 + b, bg = bg0 + bb;
                float m = am[jj][b], lv = al[jj][b];
                out[MU_OFF + (size_t)bg * LL + j] = m;
                out[LV_OFF + (size_t)bg * LL + j] = lv;
                mus[j * 32 + bb] = m;
                zs[j * 32 + bb] = fmaf(eps[(size_t)bg * LL + j], expf(0.5f * lv), m);
            }
        __syncthreads();
    }
    {
        float aa[2][4];
        #pragma unroll
        for (int jj = 0; jj < 2; jj++) {
            float bv = p1_b[j0 + jj];
            #pragma unroll
            for (int b = 0; b < 4; b++) aa[jj][b] = bv;
        }
        const float* w1 = p1_w + j0 * LL;
        #pragma unroll 1
        for (int k = 0; k < LL; k += 2) {
            float4 u = *(const float4*)(mus + k * 32 + b0);
            float4 w = *(const float4*)(mus + (k + 1) * 32 + b0);
            float va[4] = {u.x, u.y, u.z, u.w};
            float vb[4] = {w.x, w.y, w.z, w.w};
            #pragma unroll
            for (int jj = 0; jj < 2; jj++) {
                float2 a = *(const float2*)(w1 + jj * LL + k);
                #pragma unroll
                for (int b = 0; b < 4; b++) {
                    aa[jj][b] = fmaf(a.x, va[b], aa[jj][b]);
                    aa[jj][b] = fmaf(a.y, vb[b], aa[jj][b]);
                }
            }
        }
        #pragma unroll
        for (int jj = 0; jj < 2; jj++)
            #pragma unroll
            for (int b = 0; b < 4; b++)
                t1s[(j0 + jj) * 32 + b0 + b] = fmaxf(aa[jj][b], 0.0f);
        __syncthreads();
    }
    if (tid < 32) {
        float a = p2_b[0];
        for (int j = 0; j < LL; j++) a = fmaf(p2_w[j], t1s[j * 32 + tid], a);
        out[PY_OFF + bg0 + tid] = a;
    }
    for (int idx = tid; idx < GE3 * 32; idx += NTH) {
        int g = idx >> 5, b = idx & 31;
        float a = db_ih0[g];
        const float* w = dW_ih0 + g * LE;
        #pragma unroll 4
        for (int k = 0; k < LL; k++) a = fmaf(zs[k * 32 + b], w[k], a);
        gzs[idx] = a;
    }
    for (int i = tid; i < EE * 32; i += NTH) lastw[i] = 0.0f;
    __syncthreads();

    // =====================  DECODER (fp32 SIMT)  =====================
    for (int t = 0; t < TT; t++) {
        for (int idx = tid; idx < GE3 * 32; idx += NTH) {
            int g = idx >> 5, b = idx & 31;
            float a = gzs[idx];
            const float* w = dW_ih0 + g * LE + LL;
            #pragma unroll 5
            for (int k = 0; k < EE; k++) a = fmaf(lastw[k * 32 + b], w[k], a);
            g1s[idx] = a;
        }
        __syncthreads();
        for (int idx = tid; idx < EE * 32; idx += NTH) {
            int e = idx >> 5, b = idx & 31;
            float r  = sigm(g1s[e * 32 + b] + db_hh0[e]);
            float zg = sigm(g1s[(EE + e) * 32 + b] + db_hh0[EE + e]);
            float n  = tanhf(fmaf(r, db_hh0[2 * EE + e], g1s[(2 * EE + e) * 32 + b]));
            hds[idx] = (1.0f - zg) * n;
        }
        __syncthreads();
        for (int idx = tid; idx < GE3 * 32; idx += NTH) {
            int g = idx >> 5, b = idx & 31;
            float a = db_ih1[g];
            const float* w = dW_ih1 + g * EE;
            #pragma unroll 5
            for (int k = 0; k < EE; k++) a = fmaf(hds[k * 32 + b], w[k], a);
            g1s[idx] = a;
        }
        __syncthreads();
        for (int idx = tid; idx < EE * 32; idx += NTH) {
            int e = idx >> 5, b = idx & 31;
            float r  = sigm(g1s[e * 32 + b] + db_hh1[e]);
            float zg = sigm(g1s[(EE + e) * 32 + b] + db_hh1[EE + e]);
            float n  = tanhf(fmaf(r, db_hh1[2 * EE + e], g1s[(2 * EE + e) * 32 + b]));
            lastw[idx] = (1.0f - zg) * n;
        }
        __syncthreads();
        for (int idx = tid; idx < KV * 32; idx += NTH) {
            int kk = idx >> 5, b = idx & 31;
            float a = fc2_b[kk];
            const float* w = fc2_w + kk * EE;
            #pragma unroll 5
            for (int e = 0; e < EE; e++) a = fmaf(lastw[e * 32 + b], w[e], a);
            out[PRED_OFF + ((size_t)(bg0 + b) * TT + t) * KV + kk] = a;
        }
        __syncthreads();
    }
}

extern "C" void kernel_launch(void* const* d_in, const int* in_sizes, int n_in,
                              void* d_out, int out_size) {
    (void)in_sizes; (void)n_in; (void)out_size;
    const int*   x       = (const int*)  d_in[0];
    const float* emb     = (const float*)d_in[1];
    const float* eW_ih0  = (const float*)d_in[2];
    const float* eW_hh0  = (const float*)d_in[3];
    const float* eb_ih0  = (const float*)d_in[4];
    const float* eb_hh0  = (const float*)d_in[5];
    const float* eW_ih1  = (const float*)d_in[6];
    const float* eW_hh1  = (const float*)d_in[7];
    const float* eb_ih1  = (const float*)d_in[8];
    const float* eb_hh1  = (const float*)d_in[9];
    const float* dW_ih0  = (const float*)d_in[10];
    const float* db_ih0  = (const float*)d_in[12];
    const float* db_hh0  = (const float*)d_in[13];
    const float* dW_ih1  = (const float*)d_in[14];
    const float* db_ih1  = (const float*)d_in[16];
    const float* db_hh1  = (const float*)d_in[17];
    const float* fc11_w  = (const float*)d_in[18];
    const float* fc11_b  = (const float*)d_in[19];
    const float* fc12_w  = (const float*)d_in[20];
    const float* fc12_b  = (const float*)d_in[21];
    const float* p1_w    = (const float*)d_in[22];
    const float* p1_b    = (const float*)d_in[23];
    const float* p2_w    = (const float*)d_in[24];
    const float* p2_b    = (const float*)d_in[25];
    const float* fc2_w   = (const float*)d_in[26];
    const float* fc2_b   = (const float*)d_in[27];
    const float* eps     = (const float*)d_in[28];

    // one pack launch (4 matrices via blockIdx.y)
    {
        int maxtot = NTILES * NKH * 32;  // 60000
        dim3 grid((maxtot + 255) / 256, 4);
        pack_b<<<grid, 256>>>(eW_ih0, eW_hh0, eW_ih1, eW_hh1);
    }

    cudaFuncSetAttribute((const void*)vae_all,
                         cudaFuncAttributeMaxDynamicSharedMemorySize,
                         SMEM_FLOATS * (int)sizeof(float));

    vae_all<<<NCTA, NTH, SMEM_FLOATS * sizeof(float)>>>(
        x, emb, eb_ih0, eb_hh0, eb_ih1, eb_hh1,
        dW_ih0, db_ih0, db_hh0, dW_ih1, db_ih1, db_hh1,
        fc11_w, fc11_b, fc12_w, fc12_b, p1_w, p1_b, p2_w, p2_b,
        fc2_w, fc2_b, eps, (float*)d_out);
}

// round 6
// speedup vs baseline: 5.7060x; 1.7110x over previous
#include <cuda_runtime.h>
#include <cuda_fp16.h>
#include <math.h>
#include <stdint.h>

// Problem dims
#define NB 4096
#define TT 128
#define KV 64
#define EE 35
#define LL 200
#define GE3 105
#define LE 235

#define NTH 800    // 25 warps
#define BBLK 32
#define NCTA (NB / BBLK)   // 128

// fp16 m16n8k16: K=35 -> 3 k16 (pad 48); K=200 -> 13 k16 (pad 208)
#define NKIH0 3
#define NKH   13
#define NTILES 75  // 600 output rows / 8

// Output layout: concat(pred[B,T,K], mu[B,L], logvar[B,L], predY[B,1])
#define PRED_OFF ((size_t)0)
#define MU_OFF   ((size_t)NB * TT * KV)
#define LV_OFF   (MU_OFF + (size_t)NB * LL)
#define PY_OFF   (LV_OFF + (size_t)NB * LL)

// Packed fp16 B fragments: uint2 index = (tile*nk + k16)*32 + lane
// b0 = half2(W[n][k0+2tig], W[n][k0+2tig+1]), b1 = +8 rows; n = tile*8 + gid.
__device__ uint2 g_b0ih[NTILES * NKIH0 * 32];
__device__ uint2 g_b0hh[NTILES * NKH * 32];
__device__ uint2 g_b1ih[NTILES * NKH * 32];
__device__ uint2 g_b1hh[NTILES * NKH * 32];

// SMEM layout (floats)
#define HPAD 36
#define OFF_EMB 0        // 2240
#define OFF_CB  2240     // 1600 (combined biases, 2 layers x 4 x 200)
#define OFF_H1  3840     // 7200 (200 x 36 fp32)
#define OFF_H2  11040    // 7200
#define OFF_AXE 18240    // 1152 (3 k16 x 32 lanes x 12 words)
#define OFF_AH1 19392    // 4992 (13 x 32 x 12)
#define OFF_AH2 24384    // 4992
#define OFF_TOK 29376    // 4096
#define SMEM_FLOATS 33600
// decoder/head overlays (all on encoder-dead regions)
#define OFF_MUS 0        // 6400
#define OFF_T1  11040    // 6400 (over h2s; written after h2s dead)
#define OFF_ZS  18240    // 6400
#define OFF_GZ  24640    // 3360
#define OFF_G1  28000    // 3360
#define OFF_HD  31360    // 1120
#define OFF_LW  32480    // 1120

__device__ __forceinline__ float sigm(float v) { return 1.0f / (1.0f + expf(-v)); }

__device__ __forceinline__ void mma16(float (&c)[4], const uint32_t (&a)[4], uint2 b) {
    asm volatile(
        "mma.sync.aligned.m16n8k16.row.col.f32.f16.f16.f32 "
        "{%0,%1,%2,%3}, {%4,%5,%6,%7}, {%8,%9}, {%0,%1,%2,%3};"
        : "+f"(c[0]), "+f"(c[1]), "+f"(c[2]), "+f"(c[3])
        : "r"(a[0]), "r"(a[1]), "r"(a[2]), "r"(a[3]), "r"(b.x), "r"(b.y));
}

__device__ __forceinline__ uint32_t h2bits(float lo, float hi) {
    __half2 h = __floats2half2_rn(lo, hi);
    return *(uint32_t*)&h;
}

// ---- prep: pack the 4 encoder weight matrices into fp16 B-fragment layout ----
__global__ void pack_b16(const float* __restrict__ s0, const float* __restrict__ s1,
                         const float* __restrict__ s2, const float* __restrict__ s3) {
    int m = blockIdx.y;
    const float* src = (m == 0) ? s0 : (m == 1) ? s1 : (m == 2) ? s2 : s3;
    uint2* dst = (m == 0) ? g_b0ih : (m == 1) ? g_b0hh : (m == 2) ? g_b1ih : g_b1hh;
    int K  = (m == 0) ? EE : LL;
    int nk = (m == 0) ? NKIH0 : NKH;
    int idx = blockIdx.x * blockDim.x + threadIdx.x;
    int total = NTILES * nk * 32;
    if (idx >= total) return;
    int lane = idx & 31;
    int r = idx >> 5;
    int k16 = r % nk;  r /= nk;
    int tile = r;
    int gid = lane >> 2, tig = lane & 3;
    int n = tile * 8 + gid;
    int k0 = k16 * 16 + 2 * tig;
    float w00 = (k0     < K) ? src[n * K + k0]     : 0.0f;
    float w01 = (k0 + 1 < K) ? src[n * K + k0 + 1] : 0.0f;
    float w10 = (k0 + 8 < K) ? src[n * K + k0 + 8] : 0.0f;
    float w11 = (k0 + 9 < K) ? src[n * K + k0 + 9] : 0.0f;
    dst[idx] = make_uint2(h2bits(w00, w01), h2bits(w10, w11));
}

// MMA pass: acc (cr, cz, cn) over one weight matrix. A from pre-staged frag SMEM.
__device__ __forceinline__ void enc_pass(const uint32_t* __restrict__ atfA,
                                         const uint2* __restrict__ B, int nk,
                                         float (&cr)[2][4], float (&cz)[2][4], float (&cn)[2][4],
                                         int wrp, int lane)
{
    const uint2* pr = B + (size_t)(wrp * nk) * 32 + lane;
    const uint2* pz = pr + (size_t)25 * nk * 32;
    const uint2* pn = pz + (size_t)25 * nk * 32;
    #pragma unroll 1
    for (int k16 = 0; k16 < nk; k16++) {
        const uint32_t* p = atfA + (k16 * 32 + lane) * 12;
        uint4 v0 = *(const uint4*)p;
        uint4 v1 = *(const uint4*)(p + 4);
        uint32_t a[2][4] = {{v0.x, v0.y, v0.z, v0.w}, {v1.x, v1.y, v1.z, v1.w}};
        uint2 br = pr[k16 * 32];
        uint2 bz = pz[k16 * 32];
        uint2 bn = pn[k16 * 32];
        mma16(cr[0], a[0], br);  mma16(cr[1], a[1], br);
        mma16(cz[0], a[0], bz);  mma16(cz[1], a[1], bz);
        mma16(cn[0], a[0], bn);  mma16(cn[1], a[1], bn);
    }
}

// Register GRU epilogue: per-lane fragment positions of all 4 gate tiles coincide.
// Writes fp32 h (for recurrence/heads) + fp16 fragment-layout h (for next MMA).
__device__ __forceinline__ void gru_epi(float* __restrict__ hb, uint32_t* __restrict__ atf_dst,
                                        const float* __restrict__ cb,
                                        float (&cr)[2][4], float (&cz)[2][4],
                                        float (&ci)[2][4], float (&ch)[2][4],
                                        int wrp, int lane)
{
    int gid = lane >> 2, tig = lane & 3;
    int j0 = 8 * wrp + 2 * tig;
    int k16d = wrp >> 1, khalf = wrp & 1;
    uint32_t* dst = atf_dst + (k16d * 32 + lane) * 12 + khalf * 2;
    float br0 = cb[j0], br1 = cb[j0 + 1];
    float bz0 = cb[200 + j0], bz1 = cb[200 + j0 + 1];
    float bi0 = cb[400 + j0], bi1 = cb[400 + j0 + 1];
    float bh0 = cb[600 + j0], bh1 = cb[600 + j0 + 1];
    #pragma unroll
    for (int m = 0; m < 2; m++) {
        uint32_t w[2];
        #pragma unroll
        for (int bh = 0; bh < 2; bh++) {
            int b = m * 16 + bh * 8 + gid;
            float hv[2];
            #pragma unroll
            for (int d = 0; d < 2; d++) {
                int i = bh * 2 + d;
                int j = j0 + d;
                float r = sigm(cr[m][i] + (d ? br1 : br0));
                float z = sigm(cz[m][i] + (d ? bz1 : bz0));
                float n = tanhf(ci[m][i] + (d ? bi1 : bi0) + r * (ch[m][i] + (d ? bh1 : bh0)));
                float ho = hb[j * HPAD + b];
                float hn = n + z * (ho - n);
                hb[j * HPAD + b] = hn;
                hv[d] = hn;
            }
            w[bh] = h2bits(hv[0], hv[1]);
        }
        *(uint2*)(dst + m * 4) = make_uint2(w[0], w[1]);
    }
}

extern "C" __global__ void __launch_bounds__(NTH, 1)
vae_all(const int* __restrict__ x, const float* __restrict__ emb,
        const float* __restrict__ eb_ih0, const float* __restrict__ eb_hh0,
        const float* __restrict__ eb_ih1, const float* __restrict__ eb_hh1,
        const float* __restrict__ dW_ih0, const float* __restrict__ db_ih0,
        const float* __restrict__ db_hh0,
        const float* __restrict__ dW_ih1, const float* __restrict__ db_ih1,
        const float* __restrict__ db_hh1,
        const float* __restrict__ fc11_w, const float* __restrict__ fc11_b,
        const float* __restrict__ fc12_w, const float* __restrict__ fc12_b,
        const float* __restrict__ p1_w,  const float* __restrict__ p1_b,
        const float* __restrict__ p2_w,  const float* __restrict__ p2_b,
        const float* __restrict__ fc2_w, const float* __restrict__ fc2_b,
        const float* __restrict__ eps,   float* __restrict__ out)
{
    extern __shared__ float sm[];
    float* emb_s = sm + OFF_EMB;
    float* cb_s  = sm + OFF_CB;
    float* h1s   = sm + OFF_H1;
    float* h2s   = sm + OFF_H2;
    uint32_t* axe = (uint32_t*)(sm + OFF_AXE);
    uint32_t* ah1 = (uint32_t*)(sm + OFF_AH1);
    uint32_t* ah2 = (uint32_t*)(sm + OFF_AH2);
    int* toks = (int*)(sm + OFF_TOK);

    const int tid = threadIdx.x;
    const int bg0 = blockIdx.x * BBLK;

    for (int i = tid; i < KV * EE; i += NTH) emb_s[i] = emb[i];
    for (int i = tid; i < 200 * HPAD; i += NTH) { h1s[i] = 0.0f; h2s[i] = 0.0f; }
    for (int i = tid; i < 3 * 32 * 12; i += NTH) axe[i] = 0u;
    for (int i = tid; i < 13 * 32 * 12; i += NTH) { ah1[i] = 0u; ah2[i] = 0u; }
    for (int i = tid; i < TT * 32; i += NTH) {
        int t = i >> 5, b = i & 31;
        toks[i] = x[(size_t)(bg0 + b) * TT + t];
    }
    for (int i = tid; i < 1600; i += NTH) {
        int l = i / 800, rem = i % 800, g = rem / 200, j = rem % 200;
        const float* bi = l ? eb_ih1 : eb_ih0;
        const float* bh = l ? eb_hh1 : eb_hh0;
        float v;
        if      (g == 0) v = bi[j] + bh[j];
        else if (g == 1) v = bi[200 + j] + bh[200 + j];
        else if (g == 2) v = bi[400 + j];
        else             v = bh[400 + j];
        cb_s[i] = v;
    }
    __syncthreads();

    const int lane = tid & 31;
    const int wrp  = tid >> 5;

    // elementwise mapping for heads/decoder
    const int jt = tid >> 3;
    const int j0e = jt * 2;
    const int b0e = (tid & 7) * 4;

    // =====================  ENCODER (fp16 tensor cores)  =====================
    for (int t = 0; t < TT; t++) {
        // gather embeddings directly into fragment layout
        if (tid < 576) {
            int kp = tid >> 5, b = tid & 31;
            int k = kp * 2;
            int tok = toks[t * 32 + b];
            float e0 = emb_s[tok * EE + k];
            float e1 = (k + 1 < EE) ? emb_s[tok * EE + k + 1] : 0.0f;
            int jj = k & 15, k16 = k >> 4;
            int tigp = (jj & 7) >> 1, khalf = jj >> 3;
            int mhalf = (b >> 3) & 1, mt = b >> 4, gidp = b & 7;
            axe[(k16 * 32 + gidp * 4 + tigp) * 12 + mt * 4 + khalf * 2 + mhalf] = h2bits(e0, e1);
        }
        __syncthreads();

        {   // ---- layer 0 ----
            float cr[2][4] = {}, cz[2][4] = {}, ci[2][4] = {}, ch[2][4] = {};
            enc_pass(axe, g_b0ih, NKIH0, cr, cz, ci, wrp, lane);
            enc_pass(ah1, g_b0hh, NKH,   cr, cz, ch, wrp, lane);
            __syncthreads();
            gru_epi(h1s, ah1, cb_s, cr, cz, ci, ch, wrp, lane);
        }
        __syncthreads();
        {   // ---- layer 1 ----
            float cr[2][4] = {}, cz[2][4] = {}, ci[2][4] = {}, ch[2][4] = {};
            enc_pass(ah1, g_b1ih, NKH, cr, cz, ci, wrp, lane);
            enc_pass(ah2, g_b1hh, NKH, cr, cz, ch, wrp, lane);
            __syncthreads();
            gru_epi(h2s, ah2, cb_s + 800, cr, cz, ci, ch, wrp, lane);
        }
        __syncthreads();
    }

    float* mus   = sm + OFF_MUS;
    float* t1s   = sm + OFF_T1;
    float* zs    = sm + OFF_ZS;
    float* gzs   = sm + OFF_GZ;
    float* g1s   = sm + OFF_G1;
    float* hds   = sm + OFF_HD;
    float* lastw = sm + OFF_LW;

    // =====================  HEADS  =====================
    {
        float am[2][4], al[2][4];
        #pragma unroll
        for (int jj = 0; jj < 2; jj++) {
            float bm = fc11_b[j0e + jj], bl = fc12_b[j0e + jj];
            #pragma unroll
            for (int b = 0; b < 4; b++) { am[jj][b] = bm; al[jj][b] = bl; }
        }
        const float* w1 = fc11_w + j0e * LL;
        const float* w2 = fc12_w + j0e * LL;
        #pragma unroll 1
        for (int k = 0; k < LL; k += 2) {
            float4 u = *(const float4*)(h2s + k * HPAD + b0e);
            float4 w = *(const float4*)(h2s + (k + 1) * HPAD + b0e);
            float va[4] = {u.x, u.y, u.z, u.w};
            float vb[4] = {w.x, w.y, w.z, w.w};
            #pragma unroll
            for (int jj = 0; jj < 2; jj++) {
                float2 a = *(const float2*)(w1 + jj * LL + k);
                float2 c = *(const float2*)(w2 + jj * LL + k);
                #pragma unroll
                for (int b = 0; b < 4; b++) {
                    am[jj][b] = fmaf(a.x, va[b], am[jj][b]);
                    am[jj][b] = fmaf(a.y, vb[b], am[jj][b]);
                    al[jj][b] = fmaf(c.x, va[b], al[jj][b]);
                    al[jj][b] = fmaf(c.y, vb[b], al[jj][b]);
                }
            }
        }
        __syncthreads();   // all h2s reads done before overlays are written
        #pragma unroll
        for (int jj = 0; jj < 2; jj++)
            #pragma unroll
            for (int b = 0; b < 4; b++) {
                int j = j0e + jj, bb = b0e + b, bg = bg0 + bb;
                float m = am[jj][b], lv = al[jj][b];
                out[MU_OFF + (size_t)bg * LL + j] = m;
                out[LV_OFF + (size_t)bg * LL + j] = lv;
                mus[j * 32 + bb] = m;
                zs[j * 32 + bb] = fmaf(eps[(size_t)bg * LL + j], expf(0.5f * lv), m);
            }
        __syncthreads();
    }
    {
        float aa[2][4];
        #pragma unroll
        for (int jj = 0; jj < 2; jj++) {
            float bv = p1_b[j0e + jj];
            #pragma unroll
            for (int b = 0; b < 4; b++) aa[jj][b] = bv;
        }
        const float* w1 = p1_w + j0e * LL;
        #pragma unroll 1
        for (int k = 0; k < LL; k += 2) {
            float4 u = *(const float4*)(mus + k * 32 + b0e);
            float4 w = *(const float4*)(mus + (k + 1) * 32 + b0e);
            float va[4] = {u.x, u.y, u.z, u.w};
            float vb[4] = {w.x, w.y, w.z, w.w};
            #pragma unroll
            for (int jj = 0; jj < 2; jj++) {
                float2 a = *(const float2*)(w1 + jj * LL + k);
                #pragma unroll
                for (int b = 0; b < 4; b++) {
                    aa[jj][b] = fmaf(a.x, va[b], aa[jj][b]);
                    aa[jj][b] = fmaf(a.y, vb[b], aa[jj][b]);
                }
            }
        }
        #pragma unroll
        for (int jj = 0; jj < 2; jj++)
            #pragma unroll
            for (int b = 0; b < 4; b++)
                t1s[(j0e + jj) * 32 + b0e + b] = fmaxf(aa[jj][b], 0.0f);
        __syncthreads();
    }
    if (tid < 32) {
        float a = p2_b[0];
        for (int j = 0; j < LL; j++) a = fmaf(p2_w[j], t1s[j * 32 + tid], a);
        out[PY_OFF + bg0 + tid] = a;
    }
    for (int idx = tid; idx < GE3 * 32; idx += NTH) {
        int g = idx >> 5, b = idx & 31;
        float a = db_ih0[g];
        const float* w = dW_ih0 + g * LE;
        #pragma unroll 4
        for (int k = 0; k < LL; k++) a = fmaf(zs[k * 32 + b], w[k], a);
        gzs[idx] = a;
    }
    for (int i = tid; i < EE * 32; i += NTH) lastw[i] = 0.0f;
    __syncthreads();

    // =====================  DECODER (fp32 SIMT)  =====================
    for (int t = 0; t < TT; t++) {
        for (int idx = tid; idx < GE3 * 32; idx += NTH) {
            int g = idx >> 5, b = idx & 31;
            float a = gzs[idx];
            const float* w = dW_ih0 + g * LE + LL;
            #pragma unroll 5
            for (int k = 0; k < EE; k++) a = fmaf(lastw[k * 32 + b], w[k], a);
            g1s[idx] = a;
        }
        __syncthreads();
        for (int idx = tid; idx < EE * 32; idx += NTH) {
            int e = idx >> 5, b = idx & 31;
            float r  = sigm(g1s[e * 32 + b] + db_hh0[e]);
            float zg = sigm(g1s[(EE + e) * 32 + b] + db_hh0[EE + e]);
            float n  = tanhf(fmaf(r, db_hh0[2 * EE + e], g1s[(2 * EE + e) * 32 + b]));
            hds[idx] = (1.0f - zg) * n;
        }
        __syncthreads();
        for (int idx = tid; idx < GE3 * 32; idx += NTH) {
            int g = idx >> 5, b = idx & 31;
            float a = db_ih1[g];
            const float* w = dW_ih1 + g * EE;
            #pragma unroll 5
            for (int k = 0; k < EE; k++) a = fmaf(hds[k * 32 + b], w[k], a);
            g1s[idx] = a;
        }
        __syncthreads();
        for (int idx = tid; idx < EE * 32; idx += NTH) {
            int e = idx >> 5, b = idx & 31;
            float r  = sigm(g1s[e * 32 + b] + db_hh1[e]);
            float zg = sigm(g1s[(EE + e) * 32 + b] + db_hh1[EE + e]);
            float n  = tanhf(fmaf(r, db_hh1[2 * EE + e], g1s[(2 * EE + e) * 32 + b]));
            lastw[idx] = (1.0f - zg) * n;
        }
        __syncthreads();
        for (int idx = tid; idx < KV * 32; idx += NTH) {
            int kk = idx >> 5, b = idx & 31;
            float a = fc2_b[kk];
            const float* w = fc2_w + kk * EE;
            #pragma unroll 5
            for (int e = 0; e < EE; e++) a = fmaf(lastw[e * 32 + b], w[e], a);
            out[PRED_OFF + ((size_t)(bg0 + b) * TT + t) * KV + kk] = a;
        }
        __syncthreads();
    }
}

extern "C" void kernel_launch(void* const* d_in, const int* in_sizes, int n_in,
                              void* d_out, int out_size) {
    (void)in_sizes; (void)n_in; (void)out_size;
    const int*   x       = (const int*)  d_in[0];
    const float* emb     = (const float*)d_in[1];
    const float* eW_ih0  = (const float*)d_in[2];
    const float* eW_hh0  = (const float*)d_in[3];
    const float* eb_ih0  = (const float*)d_in[4];
    const float* eb_hh0  = (const float*)d_in[5];
    const float* eW_ih1  = (const float*)d_in[6];
    const float* eW_hh1  = (const float*)d_in[7];
    const float* eb_ih1  = (const float*)d_in[8];
    const float* eb_hh1  = (const float*)d_in[9];
    const float* dW_ih0  = (const float*)d_in[10];
    const float* db_ih0  = (const float*)d_in[12];
    const float* db_hh0  = (const float*)d_in[13];
    const float* dW_ih1  = (const float*)d_in[14];
    const float* db_ih1  = (const float*)d_in[16];
    const float* db_hh1  = (const float*)d_in[17];
    const float* fc11_w  = (const float*)d_in[18];
    const float* fc11_b  = (const float*)d_in[19];
    const float* fc12_w  = (const float*)d_in[20];
    const float* fc12_b  = (const float*)d_in[21];
    const float* p1_w    = (const float*)d_in[22];
    const float* p1_b    = (const float*)d_in[23];
    const float* p2_w    = (const float*)d_in[24];
    const float* p2_b    = (const float*)d_in[25];
    const float* fc2_w   = (const float*)d_in[26];
    const float* fc2_b   = (const float*)d_in[27];
    const float* eps     = (const float*)d_in[28];

    {
        int maxtot = NTILES * NKH * 32;  // 31200
        dim3 grid((maxtot + 255) / 256, 4);
        pack_b16<<<grid, 256>>>(eW_ih0, eW_hh0, eW_ih1, eW_hh1);
    }

    cudaFuncSetAttribute((const void*)vae_all,
                         cudaFuncAttributeMaxDynamicSharedMemorySize,
                         SMEM_FLOATS * (int)sizeof(float));

    vae_all<<<NCTA, NTH, SMEM_FLOATS * sizeof(float)>>>(
        x, emb, eb_ih0, eb_hh0, eb_ih1, eb_hh1,
        dW_ih0, db_ih0, db_hh0, dW_ih1, db_ih1, db_hh1,
        fc11_w, fc11_b, fc12_w, fc12_b, p1_w, p1_b, p2_w, p2_b,
        fc2_w, fc2_b, eps, (float*)d_out);
}

// round 8
// speedup vs baseline: 7.3777x; 1.2930x over previous
#include <cuda_runtime.h>
#include <cuda_fp16.h>
#include <math.h>
#include <stdint.h>

// Problem dims
#define NB 4096
#define TT 128
#define KV 64
#define EE 35
#define LL 200
#define GE3 105
#define LE 235

#define NTH 800    // 25 warps
#define BBLK 32
#define NCTA (NB / BBLK)   // 128

// fp16 m16n8k16, k16-PAIR packed B: ih0 K=35 -> 2 pairs (4 k16); hh K=200 -> 7 pairs (14 k16)
#define NP0 2
#define NPH 7
#define NTILES 75

// Output layout: concat(pred[B,T,K], mu[B,L], logvar[B,L], predY[B,1])
#define PRED_OFF ((size_t)0)
#define MU_OFF   ((size_t)NB * TT * KV)
#define LV_OFF   (MU_OFF + (size_t)NB * LL)
#define PY_OFF   (LV_OFF + (size_t)NB * LL)

// Packed fp16 B fragments, PAIRED k16: uint4 index = (tile*np + kp)*32 + lane
//   .x/.y = (b0,b1) of k16=2kp ; .z/.w = (b0,b1) of k16=2kp+1
__device__ uint4 g_b0ih[NTILES * NP0 * 32];
__device__ uint4 g_b0hh[NTILES * NPH * 32];
__device__ uint4 g_b1ih[NTILES * NPH * 32];
__device__ uint4 g_b1hh[NTILES * NPH * 32];

// SMEM layout (floats)
#define HPAD 36
#define OFF_EMB 0        // 2240
#define OFF_CB  2240     // 1600
#define OFF_H1  3840     // 7200 (200 x 36 fp32)
#define OFF_H2  11040    // 7200
#define OFF_AXE 18240    // 1536 (4 k16 x 32 x 12)
#define OFF_AH1 19776    // 5376 (14 x 32 x 12)
#define OFF_AH2 25152    // 5376
#define OFF_TOK 30528    // 4096
#define SMEM_FLOATS 34624
// ---- post-encoder overlays (regions dead at time of use; see sequencing) ----
#define OFF_MUS 0        // 6400 (heads only; dead before weights load)
#define OFF_W0  0        // 3675 dW_ih0[:,L:]   (loaded after mus dead)
#define OFF_W1  3680     // 3675 dW_ih1
#define OFF_F2T 7360     // 2240 fc2^T [35][64]
#define OFF_T1  11040    // 6400 (over h2s, after h2s reads)
#define OFF_ZS  18240    // 6400 (over axe+ah1)
#define OFF_GZ  25152    // 3360 (over ah2)
#define OFF_G1  28512    // 3360
#define OFF_HD  31872    // 1120
#define OFF_LW  32992    // 1120 -> ends 34112

__device__ __forceinline__ float sigm(float v) { return 1.0f / (1.0f + expf(-v)); }

__device__ __forceinline__ void mma16(float (&c)[4], const uint32_t (&a)[4], uint2 b) {
    asm volatile(
        "mma.sync.aligned.m16n8k16.row.col.f32.f16.f16.f32 "
        "{%0,%1,%2,%3}, {%4,%5,%6,%7}, {%8,%9}, {%0,%1,%2,%3};"
        : "+f"(c[0]), "+f"(c[1]), "+f"(c[2]), "+f"(c[3])
        : "r"(a[0]), "r"(a[1]), "r"(a[2]), "r"(a[3]), "r"(b.x), "r"(b.y));
}

__device__ __forceinline__ uint32_t h2bits(float lo, float hi) {
    __half2 h = __floats2half2_rn(lo, hi);
    return *(uint32_t*)&h;
}

// ---- prep: pack weights into paired-k16 fp16 B-fragment layout ----
__global__ void pack_b16(const float* __restrict__ s0, const float* __restrict__ s1,
                         const float* __restrict__ s2, const float* __restrict__ s3) {
    int m = blockIdx.y;
    const float* src = (m == 0) ? s0 : (m == 1) ? s1 : (m == 2) ? s2 : s3;
    uint4* dst = (m == 0) ? g_b0ih : (m == 1) ? g_b0hh : (m == 2) ? g_b1ih : g_b1hh;
    int K  = (m == 0) ? EE : LL;
    int np = (m == 0) ? NP0 : NPH;
    int idx = blockIdx.x * blockDim.x + threadIdx.x;
    int total = NTILES * np * 32;
    if (idx >= total) return;
    int lane = idx & 31;
    int r = idx >> 5;
    int kp = r % np;  r /= np;
    int tile = r;
    int gid = lane >> 2, tig = lane & 3;
    int n = tile * 8 + gid;
    float w[8];
    #pragma unroll
    for (int half = 0; half < 2; half++) {
        int kA = (2 * kp + half) * 16 + 2 * tig;
        w[half * 4 + 0] = (kA     < K) ? src[n * K + kA]     : 0.0f;
        w[half * 4 + 1] = (kA + 1 < K) ? src[n * K + kA + 1] : 0.0f;
        w[half * 4 + 2] = (kA + 8 < K) ? src[n * K + kA + 8] : 0.0f;
        w[half * 4 + 3] = (kA + 9 < K) ? src[n * K + kA + 9] : 0.0f;
    }
    dst[idx] = make_uint4(h2bits(w[0], w[1]), h2bits(w[2], w[3]),
                          h2bits(w[4], w[5]), h2bits(w[6], w[7]));
}

// MMA pass over one weight matrix (paired k16). 10 loads + 12 mma per body.
__device__ __forceinline__ void enc_pass(const uint32_t* __restrict__ atfA,
                                         const uint4* __restrict__ B, int np,
                                         float (&cr)[2][4], float (&cz)[2][4], float (&cn)[2][4],
                                         int wrp, int lane)
{
    const uint4* pr = B + (size_t)(wrp * np) * 32 + lane;
    const uint4* pz = pr + (size_t)25 * np * 32;
    const uint4* pn = pz + (size_t)25 * np * 32;
    #pragma unroll 1
    for (int kp = 0; kp < np; kp++) {
        uint4 br = pr[kp * 32];
        uint4 bz = pz[kp * 32];
        uint4 bn = pn[kp * 32];
        const uint32_t* p0 = atfA + ((2 * kp) * 32 + lane) * 12;
        const uint32_t* p1 = atfA + ((2 * kp + 1) * 32 + lane) * 12;
        uint4 v00 = *(const uint4*)p0;
        uint4 v01 = *(const uint4*)(p0 + 4);
        uint4 v10 = *(const uint4*)p1;
        uint4 v11 = *(const uint4*)(p1 + 4);
        uint32_t ae0[4] = {v00.x, v00.y, v00.z, v00.w};
        uint32_t ae1[4] = {v01.x, v01.y, v01.z, v01.w};
        uint32_t ao0[4] = {v10.x, v10.y, v10.z, v10.w};
        uint32_t ao1[4] = {v11.x, v11.y, v11.z, v11.w};
        uint2 bre = make_uint2(br.x, br.y), bro = make_uint2(br.z, br.w);
        uint2 bze = make_uint2(bz.x, bz.y), bzo = make_uint2(bz.z, bz.w);
        uint2 bne = make_uint2(bn.x, bn.y), bno = make_uint2(bn.z, bn.w);
        mma16(cr[0], ae0, bre);  mma16(cr[1], ae1, bre);
        mma16(cz[0], ae0, bze);  mma16(cz[1], ae1, bze);
        mma16(cn[0], ae0, bne);  mma16(cn[1], ae1, bne);
        mma16(cr[0], ao0, bro);  mma16(cr[1], ao1, bro);
        mma16(cz[0], ao0, bzo);  mma16(cz[1], ao1, bzo);
        mma16(cn[0], ao0, bno);  mma16(cn[1], ao1, bno);
    }
}

// Register GRU epilogue (fragment coords of all 4 gate tiles coincide).
__device__ __forceinline__ void gru_epi(float* __restrict__ hb, uint32_t* __restrict__ atf_dst,
                                        const float* __restrict__ cb,
                                        float (&cr)[2][4], float (&cz)[2][4],
                                        float (&ci)[2][4], float (&ch)[2][4],
                                        int wrp, int lane)
{
    int gid = lane >> 2, tig = lane & 3;
    int j0 = 8 * wrp + 2 * tig;
    int k16d = wrp >> 1, khalf = wrp & 1;
    uint32_t* dst = atf_dst + (k16d * 32 + lane) * 12 + khalf * 2;
    float br0 = cb[j0], br1 = cb[j0 + 1];
    float bz0 = cb[200 + j0], bz1 = cb[200 + j0 + 1];
    float bi0 = cb[400 + j0], bi1 = cb[400 + j0 + 1];
    float bh0 = cb[600 + j0], bh1 = cb[600 + j0 + 1];
    #pragma unroll
    for (int m = 0; m < 2; m++) {
        uint32_t w[2];
        #pragma unroll
        for (int bh = 0; bh < 2; bh++) {
            int b = m * 16 + bh * 8 + gid;
            float hv[2];
            #pragma unroll
            for (int d = 0; d < 2; d++) {
                int i = bh * 2 + d;
                int j = j0 + d;
                float r = sigm(cr[m][i] + (d ? br1 : br0));
                float z = sigm(cz[m][i] + (d ? bz1 : bz0));
                float n = tanhf(ci[m][i] + (d ? bi1 : bi0) + r * (ch[m][i] + (d ? bh1 : bh0)));
                float ho = hb[j * HPAD + b];
                float hn = n + z * (ho - n);
                hb[j * HPAD + b] = hn;
                hv[d] = hn;
            }
            w[bh] = h2bits(hv[0], hv[1]);
        }
        *(uint2*)(dst + m * 4) = make_uint2(w[0], w[1]);
    }
}

extern "C" __global__ void __launch_bounds__(NTH, 1)
vae_all(const int* __restrict__ x, const float* __restrict__ emb,
        const float* __restrict__ eb_ih0, const float* __restrict__ eb_hh0,
        const float* __restrict__ eb_ih1, const float* __restrict__ eb_hh1,
        const float* __restrict__ dW_ih0, const float* __restrict__ db_ih0,
        const float* __restrict__ db_hh0,
        const float* __restrict__ dW_ih1, const float* __restrict__ db_ih1,
        const float* __restrict__ db_hh1,
        const float* __restrict__ fc11_w, const float* __restrict__ fc11_b,
        const float* __restrict__ fc12_w, const float* __restrict__ fc12_b,
        const float* __restrict__ p1_w,  const float* __restrict__ p1_b,
        const float* __restrict__ p2_w,  const float* __restrict__ p2_b,
        const float* __restrict__ fc2_w, const float* __restrict__ fc2_b,
        const float* __restrict__ eps,   float* __restrict__ out)
{
    extern __shared__ float sm[];
    float* emb_s = sm + OFF_EMB;
    float* cb_s  = sm + OFF_CB;
    float* h1s   = sm + OFF_H1;
    float* h2s   = sm + OFF_H2;
    uint32_t* axe = (uint32_t*)(sm + OFF_AXE);
    uint32_t* ah1 = (uint32_t*)(sm + OFF_AH1);
    uint32_t* ah2 = (uint32_t*)(sm + OFF_AH2);
    int* toks = (int*)(sm + OFF_TOK);

    const int tid = threadIdx.x;
    const int bg0 = blockIdx.x * BBLK;

    for (int i = tid; i < KV * EE; i += NTH) emb_s[i] = emb[i];
    for (int i = tid; i < 200 * HPAD; i += NTH) { h1s[i] = 0.0f; h2s[i] = 0.0f; }
    for (int i = tid; i < 4 * 32 * 12; i += NTH) axe[i] = 0u;
    for (int i = tid; i < 14 * 32 * 12; i += NTH) { ah1[i] = 0u; ah2[i] = 0u; }
    for (int i = tid; i < TT * 32; i += NTH) {
        int t = i >> 5, b = i & 31;
        toks[i] = x[(size_t)(bg0 + b) * TT + t];
    }
    for (int i = tid; i < 1600; i += NTH) {
        int l = i / 800, rem = i % 800, g = rem / 200, j = rem % 200;
        const float* bi = l ? eb_ih1 : eb_ih0;
        const float* bh = l ? eb_hh1 : eb_hh0;
        float v;
        if      (g == 0) v = bi[j] + bh[j];
        else if (g == 1) v = bi[200 + j] + bh[200 + j];
        else if (g == 2) v = bi[400 + j];
        else             v = bh[400 + j];
        cb_s[i] = v;
    }
    __syncthreads();

    const int lane = tid & 31;
    const int wrp  = tid >> 5;

    const int jt = tid >> 3;
    const int j0e = jt * 2;
    const int b0e = (tid & 7) * 4;

    // =====================  ENCODER (fp16 mma, paired-k16 B)  =====================
    for (int t = 0; t < TT; t++) {
        if (tid < 576) {
            int kp = tid >> 5, b = tid & 31;
            int k = kp * 2;
            int tok = toks[t * 32 + b];
            float e0 = emb_s[tok * EE + k];
            float e1 = (k + 1 < EE) ? emb_s[tok * EE + k + 1] : 0.0f;
            int jj = k & 15, k16 = k >> 4;
            int tigp = (jj & 7) >> 1, khalf = jj >> 3;
            int mhalf = (b >> 3) & 1, mt = b >> 4, gidp = b & 7;
            axe[(k16 * 32 + gidp * 4 + tigp) * 12 + mt * 4 + khalf * 2 + mhalf] = h2bits(e0, e1);
        }
        __syncthreads();

        {   // ---- layer 0 ----
            float cr[2][4] = {}, cz[2][4] = {}, ci[2][4] = {}, ch[2][4] = {};
            enc_pass(axe, g_b0ih, NP0, cr, cz, ci, wrp, lane);
            enc_pass(ah1, g_b0hh, NPH, cr, cz, ch, wrp, lane);
            __syncthreads();
            gru_epi(h1s, ah1, cb_s, cr, cz, ci, ch, wrp, lane);
        }
        __syncthreads();
        {   // ---- layer 1 ----
            float cr[2][4] = {}, cz[2][4] = {}, ci[2][4] = {}, ch[2][4] = {};
            enc_pass(ah1, g_b1ih, NPH, cr, cz, ci, wrp, lane);
            enc_pass(ah2, g_b1hh, NPH, cr, cz, ch, wrp, lane);
            __syncthreads();
            gru_epi(h2s, ah2, cb_s + 800, cr, cz, ci, ch, wrp, lane);
        }
        __syncthreads();
    }

    float* mus   = sm + OFF_MUS;
    float* t1s   = sm + OFF_T1;
    float* zs    = sm + OFF_ZS;
    float* gzs   = sm + OFF_GZ;
    float* g1s   = sm + OFF_G1;
    float* hds   = sm + OFF_HD;
    float* lastw = sm + OFF_LW;
    float* w0s   = sm + OFF_W0;
    float* w1s   = sm + OFF_W1;
    float* f2t   = sm + OFF_F2T;

    // =====================  HEADS  =====================
    {
        float am[2][4], al[2][4];
        #pragma unroll
        for (int jj = 0; jj < 2; jj++) {
            float bm = fc11_b[j0e + jj], bl = fc12_b[j0e + jj];
            #pragma unroll
            for (int b = 0; b < 4; b++) { am[jj][b] = bm; al[jj][b] = bl; }
        }
        const float* w1 = fc11_w + j0e * LL;
        const float* w2 = fc12_w + j0e * LL;
        #pragma unroll 1
        for (int k = 0; k < LL; k += 2) {
            float4 u = *(const float4*)(h2s + k * HPAD + b0e);
            float4 w = *(const float4*)(h2s + (k + 1) * HPAD + b0e);
            float va[4] = {u.x, u.y, u.z, u.w};
            float vb[4] = {w.x, w.y, w.z, w.w};
            #pragma unroll
            for (int jj = 0; jj < 2; jj++) {
                float2 a = *(const float2*)(w1 + jj * LL + k);
                float2 c = *(const float2*)(w2 + jj * LL + k);
                #pragma unroll
                for (int b = 0; b < 4; b++) {
                    am[jj][b] = fmaf(a.x, va[b], am[jj][b]);
                    am[jj][b] = fmaf(a.y, vb[b], am[jj][b]);
                    al[jj][b] = fmaf(c.x, va[b], al[jj][b]);
                    al[jj][b] = fmaf(c.y, vb[b], al[jj][b]);
                }
            }
        }
        __syncthreads();   // h2s (and emb/cb/h1s) reads done before overlays
        #pragma unroll
        for (int jj = 0; jj < 2; jj++)
            #pragma unroll
            for (int b = 0; b < 4; b++) {
                int j = j0e + jj, bb = b0e + b, bg = bg0 + bb;
                float m = am[jj][b], lv = al[jj][b];
                out[MU_OFF + (size_t)bg * LL + j] = m;
                out[LV_OFF + (size_t)bg * LL + j] = lv;
                mus[j * 32 + bb] = m;
                zs[j * 32 + bb] = fmaf(eps[(size_t)bg * LL + j], expf(0.5f * lv), m);
            }
        __syncthreads();
    }
    {   // t1 = relu(mu @ p1^T + b)
        float aa[2][4];
        #pragma unroll
        for (int jj = 0; jj < 2; jj++) {
            float bv = p1_b[j0e + jj];
            #pragma unroll
            for (int b = 0; b < 4; b++) aa[jj][b] = bv;
        }
        const float* w1 = p1_w + j0e * LL;
        #pragma unroll 1
        for (int k = 0; k < LL; k += 2) {
            float4 u = *(const float4*)(mus + k * 32 + b0e);
            float4 w = *(const float4*)(mus + (k + 1) * 32 + b0e);
            float va[4] = {u.x, u.y, u.z, u.w};
            float vb[4] = {w.x, w.y, w.z, w.w};
            #pragma unroll
            for (int jj = 0; jj < 2; jj++) {
                float2 a = *(const float2*)(w1 + jj * LL + k);
                #pragma unroll
                for (int b = 0; b < 4; b++) {
                    aa[jj][b] = fmaf(a.x, va[b], aa[jj][b]);
                    aa[jj][b] = fmaf(a.y, vb[b], aa[jj][b]);
                }
            }
        }
        #pragma unroll
        for (int jj = 0; jj < 2; jj++)
            #pragma unroll
            for (int b = 0; b < 4; b++)
                t1s[(j0e + jj) * 32 + b0e + b] = fmaxf(aa[jj][b], 0.0f);
        __syncthreads();   // mus reads done; t1s visible
    }
    // predY + gz + decoder-weight staging (mus dead; zs/t1s not overlapped)
    if (tid < 32) {
        float a = p2_b[0];
        for (int j = 0; j < LL; j++) a = fmaf(p2_w[j], t1s[j * 32 + tid], a);
        out[PY_OFF + bg0 + tid] = a;
    }
    for (int idx = tid; idx < GE3 * 32; idx += NTH) {
        int g = idx >> 5, b = idx & 31;
        float a = db_ih0[g];
        const float* w = dW_ih0 + g * LE;
        #pragma unroll 4
        for (int k = 0; k < LL; k++) a = fmaf(zs[k * 32 + b], w[k], a);
        gzs[idx] = a;
    }
    for (int i = tid; i < GE3 * EE; i += NTH) {
        w0s[i] = dW_ih0[(i / EE) * LE + LL + (i % EE)];
        w1s[i] = dW_ih1[i];
    }
    for (int i = tid; i < EE * KV; i += NTH)
        f2t[i] = fc2_w[(i & 63) * EE + (i >> 6)];
    for (int i = tid; i < EE * 32; i += NTH) lastw[i] = 0.0f;
    __syncthreads();

    // =====================  DECODER (fp32 SIMT, vectorized x4)  =====================
    for (int t = 0; t < TT; t++) {
        // gi1 = gz + lastword @ dW_ih0[:, L:]^T
        for (int idx = tid; idx < GE3 * 8; idx += NTH) {
            int g = idx >> 3, b0 = (idx & 7) * 4;
            float4 acc = *(const float4*)(gzs + g * 32 + b0);
            const float* w = w0s + g * EE;
            #pragma unroll 5
            for (int k = 0; k < EE; k++) {
                float4 a = *(const float4*)(lastw + k * 32 + b0);
                float wv = w[k];
                acc.x = fmaf(wv, a.x, acc.x);
                acc.y = fmaf(wv, a.y, acc.y);
                acc.z = fmaf(wv, a.z, acc.z);
                acc.w = fmaf(wv, a.w, acc.w);
            }
            *(float4*)(g1s + g * 32 + b0) = acc;
        }
        __syncthreads();
        for (int idx = tid; idx < EE * 32; idx += NTH) {
            int e = idx >> 5, b = idx & 31;
            float r  = sigm(g1s[e * 32 + b] + db_hh0[e]);
            float zg = sigm(g1s[(EE + e) * 32 + b] + db_hh0[EE + e]);
            float n  = tanhf(fmaf(r, db_hh0[2 * EE + e], g1s[(2 * EE + e) * 32 + b]));
            hds[idx] = (1.0f - zg) * n;
        }
        __syncthreads();
        // gi2 = h1 @ dW_ih1^T + db_ih1
        for (int idx = tid; idx < GE3 * 8; idx += NTH) {
            int g = idx >> 3, b0 = (idx & 7) * 4;
            float bv = db_ih1[g];
            float4 acc = make_float4(bv, bv, bv, bv);
            const float* w = w1s + g * EE;
            #pragma unroll 5
            for (int k = 0; k < EE; k++) {
                float4 a = *(const float4*)(hds + k * 32 + b0);
                float wv = w[k];
                acc.x = fmaf(wv, a.x, acc.x);
                acc.y = fmaf(wv, a.y, acc.y);
                acc.z = fmaf(wv, a.z, acc.z);
                acc.w = fmaf(wv, a.w, acc.w);
            }
            *(float4*)(g1s + g * 32 + b0) = acc;
        }
        __syncthreads();
        for (int idx = tid; idx < EE * 32; idx += NTH) {
            int e = idx >> 5, b = idx & 31;
            float r  = sigm(g1s[e * 32 + b] + db_hh1[e]);
            float zg = sigm(g1s[(EE + e) * 32 + b] + db_hh1[EE + e]);
            float n  = tanhf(fmaf(r, db_hh1[2 * EE + e], g1s[(2 * EE + e) * 32 + b]));
            lastw[idx] = (1.0f - zg) * n;
        }
        __syncthreads();
        // pred[:, t, :] = lastword @ fc2^T + b ; fc2^T staged as f2t[e][kk]
        if (tid < 512) {
            int b = tid >> 4, kk0 = (tid & 15) * 4;
            float4 acc = *(const float4*)(fc2_b + kk0);
            #pragma unroll 5
            for (int e = 0; e < EE; e++) {
                float a = lastw[e * 32 + b];
                float4 wv = *(const float4*)(f2t + e * KV + kk0);
                acc.x = fmaf(wv.x, a, acc.x);
                acc.y = fmaf(wv.y, a, acc.y);
                acc.z = fmaf(wv.z, a, acc.z);
                acc.w = fmaf(wv.w, a, acc.w);
            }
            *(float4*)(out + PRED_OFF + ((size_t)(bg0 + b) * TT + t) * KV + kk0) = acc;
        }
        __syncthreads();
    }
}

extern "C" void kernel_launch(void* const* d_in, const int* in_sizes, int n_in,
                              void* d_out, int out_size) {
    (void)in_sizes; (void)n_in; (void)out_size;
    const int*   x       = (const int*)  d_in[0];
    const float* emb     = (const float*)d_in[1];
    const float* eW_ih0  = (const float*)d_in[2];
    const float* eW_hh0  = (const float*)d_in[3];
    const float* eb_ih0  = (const float*)d_in[4];
    const float* eb_hh0  = (const float*)d_in[5];
    const float* eW_ih1  = (const float*)d_in[6];
    const float* eW_hh1  = (const float*)d_in[7];
    const float* eb_ih1  = (const float*)d_in[8];
    const float* eb_hh1  = (const float*)d_in[9];
    const float* dW_ih0  = (const float*)d_in[10];
    const float* db_ih0  = (const float*)d_in[12];
    const float* db_hh0  = (const float*)d_in[13];
    const float* dW_ih1  = (const float*)d_in[14];
    const float* db_ih1  = (const float*)d_in[16];
    const float* db_hh1  = (const float*)d_in[17];
    const float* fc11_w  = (const float*)d_in[18];
    const float* fc11_b  = (const float*)d_in[19];
    const float* fc12_w  = (const float*)d_in[20];
    const float* fc12_b  = (const float*)d_in[21];
    const float* p1_w    = (const float*)d_in[22];
    const float* p1_b    = (const float*)d_in[23];
    const float* p2_w    = (const float*)d_in[24];
    const float* p2_b    = (const float*)d_in[25];
    const float* fc2_w   = (const float*)d_in[26];
    const float* fc2_b   = (const float*)d_in[27];
    const float* eps     = (const float*)d_in[28];

    {
        int maxtot = NTILES * NPH * 32;  // 16800
        dim3 grid((maxtot + 255) / 256, 4);
        pack_b16<<<grid, 256>>>(eW_ih0, eW_hh0, eW_ih1, eW_hh1);
    }

    cudaFuncSetAttribute((const void*)vae_all,
                         cudaFuncAttributeMaxDynamicSharedMemorySize,
                         SMEM_FLOATS * (int)sizeof(float));

    vae_all<<<NCTA, NTH, SMEM_FLOATS * sizeof(float)>>>(
        x, emb, eb_ih0, eb_hh0, eb_ih1, eb_hh1,
        dW_ih0, db_ih0, db_hh0, dW_ih1, db_ih1, db_hh1,
        fc11_w, fc11_b, fc12_w, fc12_b, p1_w, p1_b, p2_w, p2_b,
        fc2_w, fc2_b, eps, (float*)d_out);
}